// round 1
// baseline (speedup 1.0000x reference)
#include <cuda_runtime.h>

#define NN 100000
#define EE 1600000
#define DH 128
#define DOUT 40
#define BN_EPS 1e-5f

// ---------------- scratch (device globals; no runtime allocation) ----------
__device__ float g_h0[NN * DH];
__device__ float g_bA[NN * DH];
__device__ float g_bB[NN * DH];
__device__ int   g_deg[NN];
__device__ int   g_fill[NN];
__device__ float g_dinv[NN];
__device__ int   g_rowptr[NN + 1];
__device__ int   g_src[EE];
__device__ float g_val[EE];
__device__ float g_stats[2 * DH];   // [0:128) sum, [128:256) sumsq
__device__ float g_scale[DH];
__device__ float g_shift[DH];

// ---------------- graph build ----------------------------------------------
__global__ void k_zero_build() {
    int i = blockIdx.x * 256 + threadIdx.x;
    if (i < NN) { g_deg[i] = 0; g_fill[i] = 0; }
}

__global__ void k_degree(const int* __restrict__ ei) {
    int e = blockIdx.x * 256 + threadIdx.x;
    if (e < EE) atomicAdd(&g_deg[ei[EE + e]], 1);
}

__global__ void k_dinv() {
    int i = blockIdx.x * 256 + threadIdx.x;
    if (i < NN) {
        int d = g_deg[i];
        g_dinv[i] = (d > 0) ? rsqrtf((float)d) : 0.0f;
    }
}

// single-block exclusive scan of g_deg -> g_rowptr (chunked + Hillis-Steele)
__global__ void k_scan() {
    __shared__ int ss[1024];
    int t = threadIdx.x;
    const int CH = (NN + 1023) >> 10;  // 98
    int b0 = t * CH;
    int b1 = min(b0 + CH, NN);
    int s = 0;
    for (int i = b0; i < b1; ++i) s += g_deg[i];
    ss[t] = s;
    __syncthreads();
    for (int off = 1; off < 1024; off <<= 1) {
        int u = 0;
        if (t >= off) u = ss[t - off];
        __syncthreads();
        if (t >= off) ss[t] += u;
        __syncthreads();
    }
    int excl = ss[t] - s;
    int run = excl;
    for (int i = b0; i < b1; ++i) { g_rowptr[i] = run; run += g_deg[i]; }
    if (t == 1023) g_rowptr[NN] = ss[1023];
}

__global__ void k_fill(const int* __restrict__ ei) {
    int e = blockIdx.x * 256 + threadIdx.x;
    if (e >= EE) return;
    int r = ei[e];
    int c = ei[EE + e];
    int p = g_rowptr[c] + atomicAdd(&g_fill[c], 1);
    g_src[p] = r;
    g_val[p] = g_dinv[r] * g_dinv[c];
}

__global__ void k_zstats() {
    int i = threadIdx.x;
    if (i < 2 * DH) g_stats[i] = 0.0f;
}

// ---------------- GEMM 128-wide: Z = A @ W^T + b, with BN stats epilogue ---
// block (16,16), tile 128 rows x 128 cols, thread tile 8x8, full K=128 in smem
__global__ void k_gemm128(const float* __restrict__ A, const float* __restrict__ W,
                          const float* __restrict__ bias, float* __restrict__ Z,
                          int nrows) {
    extern __shared__ float sm[];
    float* As = sm;            // [128][128]  (row, k)
    float* Ws = sm + 16384;    // [128][128]  (k, j)  == W transposed
    const int tx = threadIdx.x, ty = threadIdx.y;
    const int tid = ty * 16 + tx;
    const int rowBase = blockIdx.x * 128;

    const float4* W4 = (const float4*)W;
#pragma unroll
    for (int it = 0; it < 16; ++it) {
        int vec = tid + it * 256;          // 0..4095
        int j = vec >> 5, k4 = vec & 31;
        float4 w = W4[vec];
        Ws[(k4 * 4 + 0) * 128 + j] = w.x;
        Ws[(k4 * 4 + 1) * 128 + j] = w.y;
        Ws[(k4 * 4 + 2) * 128 + j] = w.z;
        Ws[(k4 * 4 + 3) * 128 + j] = w.w;
    }
    const float4* A4 = (const float4*)A;
#pragma unroll
    for (int it = 0; it < 16; ++it) {
        int vec = tid + it * 256;
        int rr = vec >> 5, k4 = vec & 31;
        int grow = rowBase + rr;
        float4 a = make_float4(0.f, 0.f, 0.f, 0.f);
        if (grow < nrows) a = A4[(size_t)grow * 32 + k4];
        *(float4*)(As + rr * 128 + k4 * 4) = a;
    }
    __syncthreads();

    const int r0 = ty * 8, c0 = tx * 8;
    float acc[8][8];
#pragma unroll
    for (int r = 0; r < 8; ++r)
#pragma unroll
        for (int c = 0; c < 8; ++c) acc[r][c] = 0.f;

#pragma unroll 4
    for (int k = 0; k < 128; ++k) {
        float b[8];
        float4 b0 = *(const float4*)(Ws + k * 128 + c0);
        float4 b1 = *(const float4*)(Ws + k * 128 + c0 + 4);
        b[0] = b0.x; b[1] = b0.y; b[2] = b0.z; b[3] = b0.w;
        b[4] = b1.x; b[5] = b1.y; b[6] = b1.z; b[7] = b1.w;
#pragma unroll
        for (int r = 0; r < 8; ++r) {
            float a = As[(r0 + r) * 128 + k];
#pragma unroll
            for (int c = 0; c < 8; ++c) acc[r][c] = fmaf(a, b[c], acc[r][c]);
        }
    }

    float bb[8];
#pragma unroll
    for (int c = 0; c < 8; ++c) bb[c] = bias[c0 + c];

    float csum[8], csq[8];
#pragma unroll
    for (int c = 0; c < 8; ++c) { csum[c] = 0.f; csq[c] = 0.f; }

#pragma unroll
    for (int r = 0; r < 8; ++r) {
        int grow = rowBase + r0 + r;
        if (grow < nrows) {
            float z[8];
#pragma unroll
            for (int c = 0; c < 8; ++c) {
                z[c] = acc[r][c] + bb[c];
                csum[c] += z[c];
                csq[c] += z[c] * z[c];
            }
            float4* zp = (float4*)(Z + (size_t)grow * 128 + c0);
            zp[0] = make_float4(z[0], z[1], z[2], z[3]);
            zp[1] = make_float4(z[4], z[5], z[6], z[7]);
        }
    }

    // block-level stats reduction (reuse smem)
    __syncthreads();
    float* rs = sm;            // [16][128]
    float* rq = sm + 2048;     // [16][128]
#pragma unroll
    for (int c = 0; c < 8; ++c) {
        rs[ty * 128 + c0 + c] = csum[c];
        rq[ty * 128 + c0 + c] = csq[c];
    }
    __syncthreads();
    if (tid < 128) {
        float s = 0.f, q = 0.f;
#pragma unroll
        for (int t = 0; t < 16; ++t) { s += rs[t * 128 + tid]; q += rq[t * 128 + tid]; }
        atomicAdd(&g_stats[tid], s);
        atomicAdd(&g_stats[128 + tid], q);
    }
}

// ---------------- BN prep + fused BN/ReLU/residual -------------------------
__global__ void k_bnprep(const float* __restrict__ gamma, const float* __restrict__ beta) {
    int j = threadIdx.x;
    if (j < DH) {
        float mu = g_stats[j] * (1.0f / (float)NN);
        float var = g_stats[128 + j] * (1.0f / (float)NN) - mu * mu;
        float rs = rsqrtf(var + BN_EPS);
        float sc = gamma[j] * rs;
        g_scale[j] = sc;
        g_shift[j] = beta[j] - mu * sc;
    }
}

__global__ void k_bnrelu(const float4* __restrict__ Z, const float4* __restrict__ X0,
                         float4* __restrict__ H, int nvec, int hasres) {
    int i = blockIdx.x * 256 + threadIdx.x;
    if (i >= nvec) return;
    int c4 = i & 31;
    float4 sc = ((const float4*)g_scale)[c4];
    float4 sh = ((const float4*)g_shift)[c4];
    float4 z = Z[i];
    float4 h;
    h.x = fmaxf(fmaf(z.x, sc.x, sh.x), 0.f);
    h.y = fmaxf(fmaf(z.y, sc.y, sh.y), 0.f);
    h.z = fmaxf(fmaf(z.z, sc.z, sh.z), 0.f);
    h.w = fmaxf(fmaf(z.w, sc.w, sh.w), 0.f);
    if (hasres) {
        float4 x0 = X0[i];
        h.x += x0.x; h.y += x0.y; h.z += x0.z; h.w += x0.w;
    }
    H[i] = h;
}

// ---------------- SPMM: OUT[v] = sum_{e in CSR[v]} val[e] * H[src[e]] ------
// one warp per destination node, float4 per lane (128 features)
__global__ void k_spmm(const float4* __restrict__ H, float4* __restrict__ O) {
    int gt = blockIdx.x * 256 + threadIdx.x;
    int w = gt >> 5;
    int lane = gt & 31;
    if (w >= NN) return;
    int rp0 = g_rowptr[w], rp1 = g_rowptr[w + 1];
    float4 acc = make_float4(0.f, 0.f, 0.f, 0.f);
    for (int base = rp0; base < rp1; base += 32) {
        int nb = min(32, rp1 - base);
        int s = 0; float v = 0.f;
        if (lane < nb) { s = g_src[base + lane]; v = g_val[base + lane]; }
        for (int j = 0; j < nb; ++j) {
            int sj = __shfl_sync(0xffffffffu, s, j);
            float vj = __shfl_sync(0xffffffffu, v, j);
            float4 hv = H[(size_t)sj * 32 + lane];
            acc.x = fmaf(vj, hv.x, acc.x);
            acc.y = fmaf(vj, hv.y, acc.y);
            acc.z = fmaf(vj, hv.z, acc.z);
            acc.w = fmaf(vj, hv.w, acc.w);
        }
    }
    O[(size_t)w * 32 + lane] = acc;
}

// ---------------- classifier: out = H @ cls_w^T + cls_b (N x 40) -----------
// block (8,16), tile 128 rows x 40 cols, thread tile 8x5
__global__ void k_cls(const float* __restrict__ A, const float* __restrict__ W,
                      const float* __restrict__ bias, float* __restrict__ O, int nrows) {
    extern __shared__ float sm[];
    float* As = sm;             // [128][128]
    float* Wt = sm + 16384;     // [128][40]  (k, j)
    const int tx = threadIdx.x, ty = threadIdx.y;
    const int tid = ty * 8 + tx;  // 128 threads
    const int rowBase = blockIdx.x * 128;

    for (int idx = tid; idx < DOUT * DH; idx += 128) {
        int j = idx >> 7, k = idx & 127;
        Wt[k * DOUT + j] = W[idx];
    }
    const float4* A4 = (const float4*)A;
#pragma unroll
    for (int it = 0; it < 32; ++it) {
        int vec = tid + it * 128;
        int rr = vec >> 5, k4 = vec & 31;
        int grow = rowBase + rr;
        float4 a = make_float4(0.f, 0.f, 0.f, 0.f);
        if (grow < nrows) a = A4[(size_t)grow * 32 + k4];
        *(float4*)(As + rr * 128 + k4 * 4) = a;
    }
    __syncthreads();

    const int r0 = ty * 8, c0 = tx * 5;
    float acc[8][5];
#pragma unroll
    for (int r = 0; r < 8; ++r)
#pragma unroll
        for (int c = 0; c < 5; ++c) acc[r][c] = 0.f;

#pragma unroll 4
    for (int k = 0; k < 128; ++k) {
        float b[5];
#pragma unroll
        for (int c = 0; c < 5; ++c) b[c] = Wt[k * DOUT + c0 + c];
#pragma unroll
        for (int r = 0; r < 8; ++r) {
            float a = As[(r0 + r) * 128 + k];
#pragma unroll
            for (int c = 0; c < 5; ++c) acc[r][c] = fmaf(a, b[c], acc[r][c]);
        }
    }
    float bb[5];
#pragma unroll
    for (int c = 0; c < 5; ++c) bb[c] = bias[c0 + c];
#pragma unroll
    for (int r = 0; r < 8; ++r) {
        int grow = rowBase + r0 + r;
        if (grow < nrows) {
#pragma unroll
            for (int c = 0; c < 5; ++c)
                O[(size_t)grow * DOUT + c0 + c] = acc[r][c] + bb[c];
        }
    }
}

// ---------------- driver ----------------------------------------------------
extern "C" void kernel_launch(void* const* d_in, const int* in_sizes, int n_in,
                              void* d_out, int out_size) {
    const float* x      = (const float*)d_in[0];
    const int*   ei     = (const int*)d_in[1];
    const float* fc_w   = (const float*)d_in[2];
    const float* fc_b   = (const float*)d_in[3];
    const float* conv_w = (const float*)d_in[4];
    const float* conv_b = (const float*)d_in[5];
    const float* gamma  = (const float*)d_in[6];
    const float* beta   = (const float*)d_in[7];
    const float* cls_w  = (const float*)d_in[8];
    const float* cls_b  = (const float*)d_in[9];
    float* out = (float*)d_out;

    float *h0, *bA, *bB;
    cudaGetSymbolAddress((void**)&h0, g_h0);
    cudaGetSymbolAddress((void**)&bA, g_bA);
    cudaGetSymbolAddress((void**)&bB, g_bB);

    const int GEMM_SMEM = 2 * 128 * 128 * 4;                 // 131072
    const int CLS_SMEM  = 128 * 128 * 4 + DH * DOUT * 4;     // 86016
    cudaFuncSetAttribute(k_gemm128, cudaFuncAttributeMaxDynamicSharedMemorySize, GEMM_SMEM);
    cudaFuncSetAttribute(k_cls,     cudaFuncAttributeMaxDynamicSharedMemorySize, CLS_SMEM);

    const int nodeBlocks = (NN + 255) / 256;
    const int edgeBlocks = (EE + 255) / 256;
    const int gemmGrid   = (NN + 127) / 128;
    const int vecBlocks  = (NN * 32) / 256;  // 12500 (exact)

    // graph build (per-launch, deterministic within fp tolerance)
    k_zero_build<<<nodeBlocks, 256>>>();
    k_degree<<<edgeBlocks, 256>>>(ei);
    k_dinv<<<nodeBlocks, 256>>>();
    k_scan<<<1, 1024>>>();
    k_fill<<<edgeBlocks, 256>>>(ei);

    dim3 gblk(16, 16);

    // layer 0: fc -> bn0 -> relu  (writes x0 = h0)
    k_zstats<<<1, 256>>>();
    k_gemm128<<<gemmGrid, gblk, GEMM_SMEM>>>(x, fc_w, fc_b, bB, NN);
    k_bnprep<<<1, 128>>>(gamma, beta);
    k_bnrelu<<<vecBlocks, 256>>>((const float4*)bB, (const float4*)0, (float4*)h0, NN * 32, 0);

    const float* hin = h0;
    float* ping = bA;
    float* pong = bB;
    for (int i = 0; i < 3; ++i) {
        k_spmm<<<vecBlocks, 256>>>((const float4*)hin, (float4*)ping);
        k_zstats<<<1, 256>>>();
        k_gemm128<<<gemmGrid, gblk, GEMM_SMEM>>>(ping, conv_w + i * DH * DH,
                                                 conv_b + i * DH, pong, NN);
        k_bnprep<<<1, 128>>>(gamma + (i + 1) * DH, beta + (i + 1) * DH);
        k_bnrelu<<<vecBlocks, 256>>>((const float4*)pong, (const float4*)h0,
                                     (float4*)ping, NN * 32, 1);
        hin = ping;
        float* t = ping; ping = pong; pong = t;
    }

    k_cls<<<gemmGrid, dim3(8, 16), CLS_SMEM>>>(hin, cls_w, cls_b, out, NN);
}

// round 3
// speedup vs baseline: 1.4669x; 1.4669x over previous
#include <cuda_runtime.h>
#include <cstdint>

#define NN 100000
#define EE 1600000
#define DH 128
#define DOUT 40
#define BN_EPS 1e-5f
#define AST 132   // padded smem row stride (floats) -> conflict-free frag loads

// ===================== scratch ==============================================
__device__ float g_h0[NN * DH];
__device__ float g_bA[NN * DH];
__device__ float g_bB[NN * DH];
__device__ int   g_deg[NN];
__device__ int   g_fill[NN];
__device__ float g_dinv[NN];
__device__ int   g_rowptr[NN + 1];
__device__ int2  g_edge[EE];       // {src, float bits of val}
__device__ int   g_bsum[128];
__device__ int   g_boff[128];
__device__ float g_stats[2 * DH];
__device__ float g_scale[DH];
__device__ float g_shift[DH];

// ===================== graph build ==========================================
__global__ void k_zero_build() {
    int i = blockIdx.x * 256 + threadIdx.x;
    if (i < NN) { g_deg[i] = 0; g_fill[i] = 0; }
}

__global__ void k_degree(const int* __restrict__ ei) {
    int e = blockIdx.x * 256 + threadIdx.x;
    if (e < EE) atomicAdd(&g_deg[ei[EE + e]], 1);
}

// partial scan: grid 98 x 256, 4 elems/thread; also computes dinv
__global__ void k_scan_part() {
    __shared__ int ws[8];
    int t = threadIdx.x, b = blockIdx.x;
    int base = b * 1024 + t * 4;
    int4 d = make_int4(0, 0, 0, 0);
    if (base + 3 < NN) d = *(const int4*)&g_deg[base];
    else {
        if (base + 0 < NN) d.x = g_deg[base + 0];
        if (base + 1 < NN) d.y = g_deg[base + 1];
        if (base + 2 < NN) d.z = g_deg[base + 2];
    }
    float4 dv;
    dv.x = d.x > 0 ? rsqrtf((float)d.x) : 0.f;
    dv.y = d.y > 0 ? rsqrtf((float)d.y) : 0.f;
    dv.z = d.z > 0 ? rsqrtf((float)d.z) : 0.f;
    dv.w = d.w > 0 ? rsqrtf((float)d.w) : 0.f;
    if (base + 3 < NN) *(float4*)&g_dinv[base] = dv;
    else {
        if (base + 0 < NN) g_dinv[base + 0] = dv.x;
        if (base + 1 < NN) g_dinv[base + 1] = dv.y;
        if (base + 2 < NN) g_dinv[base + 2] = dv.z;
    }
    int s = d.x + d.y + d.z + d.w;
    int lane = t & 31, wid = t >> 5;
    int sc = s;
#pragma unroll
    for (int o = 1; o < 32; o <<= 1) {
        int u = __shfl_up_sync(0xffffffffu, sc, o);
        if (lane >= o) sc += u;
    }
    if (lane == 31) ws[wid] = sc;
    __syncthreads();
    if (t < 8) {
        int v = ws[t];
#pragma unroll
        for (int o = 1; o < 8; o <<= 1) {
            int u = __shfl_up_sync(0xffu, v, o);
            if (t >= o) v += u;
        }
        ws[t] = v;
    }
    __syncthreads();
    int excl = sc - s + (wid ? ws[wid - 1] : 0);
    int4 rp;
    rp.x = excl; rp.y = excl + d.x; rp.z = rp.y + d.y; rp.w = rp.z + d.z;
    if (base + 3 < NN) *(int4*)&g_rowptr[base] = rp;
    else {
        if (base + 0 < NN) g_rowptr[base + 0] = rp.x;
        if (base + 1 < NN) g_rowptr[base + 1] = rp.y;
        if (base + 2 < NN) g_rowptr[base + 2] = rp.z;
    }
    if (t == 255) g_bsum[b] = excl + s;
}

__global__ void k_scan_tots(int nblk) {   // 1 warp
    int lane = threadIdx.x;
    int carry = 0;
    for (int i = 0; i < 4; ++i) {
        int idx = i * 32 + lane;
        int v = idx < nblk ? g_bsum[idx] : 0;
        int sc = v;
#pragma unroll
        for (int o = 1; o < 32; o <<= 1) {
            int u = __shfl_up_sync(0xffffffffu, sc, o);
            if (lane >= o) sc += u;
        }
        if (idx < nblk) g_boff[idx] = carry + sc - v;
        carry += __shfl_sync(0xffffffffu, sc, 31);
    }
    if (lane == 0) g_rowptr[NN] = carry;
}

__global__ void k_scan_add() {
    int t = threadIdx.x, b = blockIdx.x;
    if (b == 0) return;
    int off = g_boff[b];
    int base = b * 1024 + t * 4;
    if (base + 3 < NN) {
        int4 rp = *(const int4*)&g_rowptr[base];
        rp.x += off; rp.y += off; rp.z += off; rp.w += off;
        *(int4*)&g_rowptr[base] = rp;
    } else {
        for (int i = 0; i < 4; ++i)
            if (base + i < NN) g_rowptr[base + i] += off;
    }
}

__global__ void k_fill(const int* __restrict__ ei) {
    int e = blockIdx.x * 256 + threadIdx.x;
    if (e >= EE) return;
    int r = ei[e];
    int c = ei[EE + e];
    int p = g_rowptr[c] + atomicAdd(&g_fill[c], 1);
    float v = g_dinv[r] * g_dinv[c];
    g_edge[p] = make_int2(r, __float_as_int(v));
}

__global__ void k_zstats() {
    int i = threadIdx.x;
    if (i < 2 * DH) g_stats[i] = 0.0f;
}

// ===================== tf32 mma.sync GEMM (3xTF32 split) ====================
// Z = A @ W^T + b ; BN stats epilogue. tile 128x128xK128, 8 warps (4m x 2n),
// warp tile 32x64, mma m16n8k8, split: AhBh + AhBl + AlBh.

__device__ __forceinline__ void splitf(float x, uint32_t& h, uint32_t& l) {
    uint32_t xb = __float_as_uint(x);
    uint32_t hb = xb & 0xFFFFE000u;     // exact tf32-truncated hi
    h = hb;
    l = __float_as_uint(x - __uint_as_float(hb));
}

__device__ __forceinline__ void mma8(float* d, const uint32_t* a, uint32_t b0, uint32_t b1) {
    asm volatile(
        "mma.sync.aligned.m16n8k8.row.col.f32.tf32.tf32.f32 "
        "{%0,%1,%2,%3}, {%4,%5,%6,%7}, {%8,%9}, {%0,%1,%2,%3};"
        : "+f"(d[0]), "+f"(d[1]), "+f"(d[2]), "+f"(d[3])
        : "r"(a[0]), "r"(a[1]), "r"(a[2]), "r"(a[3]), "r"(b0), "r"(b1));
}

#define GEMM_SMEM ((2 * 128 * AST + 3 * 128) * 4)

__global__ __launch_bounds__(256)
void k_gemm_mma(const float* __restrict__ A, const float* __restrict__ W,
                const float* __restrict__ bias, float* __restrict__ Z, int nrows) {
    extern __shared__ float sm[];
    float* sA    = sm;                    // [128][AST]
    float* sB    = sm + 128 * AST;        // [128][AST]
    float* sSum  = sm + 2 * 128 * AST;    // [128]
    float* sSq   = sSum + 128;            // [128]
    float* sBias = sSq + 128;             // [128]

    const int tid = threadIdx.x;
    const int wid = tid >> 5, lane = tid & 31;
    const int rowBase = blockIdx.x * 128;
    const int r = lane >> 2, c = lane & 3;

    const float4* A4 = (const float4*)A;
#pragma unroll
    for (int it = 0; it < 16; ++it) {
        int vec = tid + it * 256;
        int row = vec >> 5, q = vec & 31;
        int gr = rowBase + row;
        float4 v = make_float4(0.f, 0.f, 0.f, 0.f);
        if (gr < nrows) v = A4[(size_t)gr * 32 + q];
        *(float4*)&sA[row * AST + q * 4] = v;
    }
    const float4* W4 = (const float4*)W;
#pragma unroll
    for (int it = 0; it < 16; ++it) {
        int vec = tid + it * 256;
        int row = vec >> 5, q = vec & 31;
        float4 v = W4[vec];
        *(float4*)&sB[row * AST + q * 4] = v;
    }
    if (tid < 128) { sSum[tid] = 0.f; sSq[tid] = 0.f; sBias[tid] = bias[tid]; }
    __syncthreads();

    const int wm = wid & 3, wn = wid >> 2;
    float acc[2][8][4];
#pragma unroll
    for (int mt = 0; mt < 2; ++mt)
#pragma unroll
        for (int nt = 0; nt < 8; ++nt)
#pragma unroll
            for (int i = 0; i < 4; ++i) acc[mt][nt][i] = 0.f;

    const int aBase = (wm * 32 + r) * AST + c;
    const int bBase = (wn * 64 + r) * AST + c;

#pragma unroll 1
    for (int ks = 0; ks < 16; ++ks) {
        const int kb = ks * 8;
        uint32_t ah[2][4], al[2][4];
#pragma unroll
        for (int mt = 0; mt < 2; ++mt) {
            int ba = aBase + mt * 16 * AST + kb;
            splitf(sA[ba],               ah[mt][0], al[mt][0]);
            splitf(sA[ba + 8 * AST],     ah[mt][1], al[mt][1]);
            splitf(sA[ba + 4],           ah[mt][2], al[mt][2]);
            splitf(sA[ba + 8 * AST + 4], ah[mt][3], al[mt][3]);
        }
#pragma unroll
        for (int nt = 0; nt < 8; ++nt) {
            int bb = bBase + nt * 8 * AST + kb;
            uint32_t bh0, bl0, bh1, bl1;
            splitf(sB[bb],     bh0, bl0);
            splitf(sB[bb + 4], bh1, bl1);
#pragma unroll
            for (int mt = 0; mt < 2; ++mt) {
                mma8(acc[mt][nt], ah[mt], bh0, bh1);
                mma8(acc[mt][nt], ah[mt], bl0, bl1);
                mma8(acc[mt][nt], al[mt], bh0, bh1);
            }
        }
    }

    // epilogue: bias add, store, BN stats
    float cs[16], cq[16];
#pragma unroll
    for (int i = 0; i < 16; ++i) { cs[i] = 0.f; cq[i] = 0.f; }

#pragma unroll
    for (int nt = 0; nt < 8; ++nt) {
        int C0 = wn * 64 + nt * 8 + 2 * c;
        float b0 = sBias[C0], b1 = sBias[C0 + 1];
#pragma unroll
        for (int mt = 0; mt < 2; ++mt) {
            int R0 = rowBase + wm * 32 + mt * 16 + r;
            int R1 = R0 + 8;
            if (R0 < nrows) {
                float z0 = acc[mt][nt][0] + b0;
                float z1 = acc[mt][nt][1] + b1;
                *(float2*)&Z[(size_t)R0 * 128 + C0] = make_float2(z0, z1);
                cs[2 * nt] += z0; cq[2 * nt] += z0 * z0;
                cs[2 * nt + 1] += z1; cq[2 * nt + 1] += z1 * z1;
            }
            if (R1 < nrows) {
                float z2 = acc[mt][nt][2] + b0;
                float z3 = acc[mt][nt][3] + b1;
                *(float2*)&Z[(size_t)R1 * 128 + C0] = make_float2(z2, z3);
                cs[2 * nt] += z2; cq[2 * nt] += z2 * z2;
                cs[2 * nt + 1] += z3; cq[2 * nt + 1] += z3 * z3;
            }
        }
    }
    // reduce across lanes with same c (fold r): xor 4, 8, 16
#pragma unroll
    for (int o = 4; o <= 16; o <<= 1) {
#pragma unroll
        for (int i = 0; i < 16; ++i) {
            cs[i] += __shfl_xor_sync(0xffffffffu, cs[i], o);
            cq[i] += __shfl_xor_sync(0xffffffffu, cq[i], o);
        }
    }
    if (r == 0) {
#pragma unroll
        for (int nt = 0; nt < 8; ++nt) {
            int C0 = wn * 64 + nt * 8 + 2 * c;
            atomicAdd(&sSum[C0],     cs[2 * nt]);
            atomicAdd(&sSum[C0 + 1], cs[2 * nt + 1]);
            atomicAdd(&sSq[C0],      cq[2 * nt]);
            atomicAdd(&sSq[C0 + 1],  cq[2 * nt + 1]);
        }
    }
    __syncthreads();
    if (tid < 128) {
        atomicAdd(&g_stats[tid], sSum[tid]);
        atomicAdd(&g_stats[128 + tid], sSq[tid]);
    }
}

// ===================== BN prep + fused BN/ReLU/residual =====================
__global__ void k_bnprep(const float* __restrict__ gamma, const float* __restrict__ beta) {
    int j = threadIdx.x;
    if (j < DH) {
        float mu = g_stats[j] * (1.0f / (float)NN);
        float var = g_stats[128 + j] * (1.0f / (float)NN) - mu * mu;
        float rs = rsqrtf(var + BN_EPS);
        float sc = gamma[j] * rs;
        g_scale[j] = sc;
        g_shift[j] = beta[j] - mu * sc;
    }
}

__global__ void k_bnrelu(const float4* __restrict__ Z, const float4* __restrict__ X0,
                         float4* __restrict__ H, int nvec, int hasres) {
    int i = blockIdx.x * 256 + threadIdx.x;
    if (i >= nvec) return;
    int c4 = i & 31;
    float4 sc = ((const float4*)g_scale)[c4];
    float4 sh = ((const float4*)g_shift)[c4];
    float4 z = Z[i];
    float4 h;
    h.x = fmaxf(fmaf(z.x, sc.x, sh.x), 0.f);
    h.y = fmaxf(fmaf(z.y, sc.y, sh.y), 0.f);
    h.z = fmaxf(fmaf(z.z, sc.z, sh.z), 0.f);
    h.w = fmaxf(fmaf(z.w, sc.w, sh.w), 0.f);
    if (hasres) {
        float4 x0 = X0[i];
        h.x += x0.x; h.y += x0.y; h.z += x0.z; h.w += x0.w;
    }
    H[i] = h;
}

// ===================== SPMM (warp per node, CSR gather) =====================
__global__ void k_spmm(const float4* __restrict__ H, float4* __restrict__ O) {
    int gt = blockIdx.x * 256 + threadIdx.x;
    int w = gt >> 5;
    int lane = gt & 31;
    if (w >= NN) return;
    int rp0 = g_rowptr[w], rp1 = g_rowptr[w + 1];
    float4 acc = make_float4(0.f, 0.f, 0.f, 0.f);
    for (int base = rp0; base < rp1; base += 32) {
        int nb = min(32, rp1 - base);
        int s = 0; float v = 0.f;
        if (lane < nb) {
            int2 e = g_edge[base + lane];
            s = e.x; v = __int_as_float(e.y);
        }
        for (int j = 0; j < nb; ++j) {
            int sj = __shfl_sync(0xffffffffu, s, j);
            float vj = __shfl_sync(0xffffffffu, v, j);
            float4 hv = H[(size_t)sj * 32 + lane];
            acc.x = fmaf(vj, hv.x, acc.x);
            acc.y = fmaf(vj, hv.y, acc.y);
            acc.z = fmaf(vj, hv.z, acc.z);
            acc.w = fmaf(vj, hv.w, acc.w);
        }
    }
    O[(size_t)w * 32 + lane] = acc;
}

// ===================== classifier (N x 40, scalar FMA) ======================
__global__ void k_cls(const float* __restrict__ A, const float* __restrict__ W,
                      const float* __restrict__ bias, float* __restrict__ O, int nrows) {
    extern __shared__ float sm[];
    float* As = sm;             // [128][128]
    float* Wt = sm + 16384;     // [128][40]
    const int tx = threadIdx.x, ty = threadIdx.y;
    const int tid = ty * 8 + tx;
    const int rowBase = blockIdx.x * 128;

    for (int idx = tid; idx < DOUT * DH; idx += 128) {
        int j = idx >> 7, k = idx & 127;
        Wt[k * DOUT + j] = W[idx];
    }
    const float4* A4 = (const float4*)A;
#pragma unroll
    for (int it = 0; it < 32; ++it) {
        int vec = tid + it * 128;
        int rr = vec >> 5, k4 = vec & 31;
        int grow = rowBase + rr;
        float4 a = make_float4(0.f, 0.f, 0.f, 0.f);
        if (grow < nrows) a = A4[(size_t)grow * 32 + k4];
        *(float4*)(As + rr * 128 + k4 * 4) = a;
    }
    __syncthreads();

    const int r0 = ty * 8, c0 = tx * 5;
    float acc[8][5];
#pragma unroll
    for (int r = 0; r < 8; ++r)
#pragma unroll
        for (int c = 0; c < 5; ++c) acc[r][c] = 0.f;

#pragma unroll 4
    for (int k = 0; k < 128; ++k) {
        float b[5];
#pragma unroll
        for (int c = 0; c < 5; ++c) b[c] = Wt[k * DOUT + c0 + c];
#pragma unroll
        for (int r = 0; r < 8; ++r) {
            float a = As[(r0 + r) * 128 + k];
#pragma unroll
            for (int c = 0; c < 5; ++c) acc[r][c] = fmaf(a, b[c], acc[r][c]);
        }
    }
    float bb[5];
#pragma unroll
    for (int c = 0; c < 5; ++c) bb[c] = bias[c0 + c];
#pragma unroll
    for (int r = 0; r < 8; ++r) {
        int grow = rowBase + r0 + r;
        if (grow < nrows) {
#pragma unroll
            for (int c = 0; c < 5; ++c)
                O[(size_t)grow * DOUT + c0 + c] = acc[r][c] + bb[c];
        }
    }
}

// ===================== driver ===============================================
extern "C" void kernel_launch(void* const* d_in, const int* in_sizes, int n_in,
                              void* d_out, int out_size) {
    const float* x      = (const float*)d_in[0];
    const int*   ei     = (const int*)d_in[1];
    const float* fc_w   = (const float*)d_in[2];
    const float* fc_b   = (const float*)d_in[3];
    const float* conv_w = (const float*)d_in[4];
    const float* conv_b = (const float*)d_in[5];
    const float* gamma  = (const float*)d_in[6];
    const float* beta   = (const float*)d_in[7];
    const float* cls_w  = (const float*)d_in[8];
    const float* cls_b  = (const float*)d_in[9];
    float* out = (float*)d_out;

    float *h0, *bA, *bB;
    cudaGetSymbolAddress((void**)&h0, g_h0);
    cudaGetSymbolAddress((void**)&bA, g_bA);
    cudaGetSymbolAddress((void**)&bB, g_bB);

    const int CLS_SMEM = 128 * 128 * 4 + DH * DOUT * 4;
    cudaFuncSetAttribute(k_gemm_mma, cudaFuncAttributeMaxDynamicSharedMemorySize, GEMM_SMEM);
    cudaFuncSetAttribute(k_cls,      cudaFuncAttributeMaxDynamicSharedMemorySize, CLS_SMEM);

    const int nodeBlocks = (NN + 255) / 256;
    const int edgeBlocks = (EE + 255) / 256;
    const int scanBlocks = (NN + 1023) / 1024;  // 98
    const int gemmGrid   = (NN + 127) / 128;    // 782
    const int vecBlocks  = (NN * 32) / 256;     // 12500

    // graph build
    k_zero_build<<<nodeBlocks, 256>>>();
    k_degree<<<edgeBlocks, 256>>>(ei);
    k_scan_part<<<scanBlocks, 256>>>();
    k_scan_tots<<<1, 32>>>(scanBlocks);
    k_scan_add<<<scanBlocks, 256>>>();
    k_fill<<<edgeBlocks, 256>>>(ei);

    // layer 0: fc -> bn0 -> relu  (x0 = h0)
    k_zstats<<<1, 256>>>();
    k_gemm_mma<<<gemmGrid, 256, GEMM_SMEM>>>(x, fc_w, fc_b, bB, NN);
    k_bnprep<<<1, 128>>>(gamma, beta);
    k_bnrelu<<<vecBlocks, 256>>>((const float4*)bB, (const float4*)0, (float4*)h0, NN * 32, 0);

    const float* hin = h0;
    float* ping = bA;
    float* pong = bB;
    for (int i = 0; i < 3; ++i) {
        k_spmm<<<vecBlocks, 256>>>((const float4*)hin, (float4*)ping);
        k_zstats<<<1, 256>>>();
        k_gemm_mma<<<gemmGrid, 256, GEMM_SMEM>>>(ping, conv_w + i * DH * DH,
                                                 conv_b + i * DH, pong, NN);
        k_bnprep<<<1, 128>>>(gamma + (i + 1) * DH, beta + (i + 1) * DH);
        k_bnrelu<<<vecBlocks, 256>>>((const float4*)pong, (const float4*)h0,
                                     (float4*)ping, NN * 32, 1);
        hin = ping;
        float* t = ping; ping = pong; pong = t;
    }

    k_cls<<<gemmGrid, dim3(8, 16), CLS_SMEM>>>(hin, cls_w, cls_b, out, NN);
}

// round 4
// speedup vs baseline: 1.5429x; 1.0518x over previous
#include <cuda_runtime.h>
#include <cuda_fp16.h>
#include <cstdint>

#define NN 100000
#define EE 1600000
#define DH 128
#define DOUT 40
#define BN_EPS 1e-5f
#define AST 132   // padded smem row stride (floats) -> conflict-free frag loads

// ===================== scratch ==============================================
__device__ float  g_h0f[NN * DH];   // x0 residual, fp32 (exact)
__device__ __half g_hH[NN * DH];    // current h for SPMM gather (fp16)
__device__ float  g_bA[NN * DH];    // agg (and final h3)
__device__ float  g_bB[NN * DH];    // z = GEMM output
__device__ int    g_deg[NN];
__device__ int    g_fill[NN];
__device__ float  g_dinv[NN];
__device__ int    g_rowptr[NN + 1];
__device__ int2   g_edge[EE];       // {src, float bits of val}
__device__ int    g_bsum[128];
__device__ int    g_boff[128];
__device__ float  g_stats[2 * DH];  // zero at start of each replay (bnprep re-zeroes)
__device__ float  g_scale[DH];
__device__ float  g_shift[DH];

// ===================== graph build ==========================================
__global__ void k_zero_build() {
    int i = blockIdx.x * 256 + threadIdx.x;
    if (i < NN) { g_deg[i] = 0; g_fill[i] = 0; }
}

__global__ void k_degree(const int* __restrict__ ei) {
    int e = blockIdx.x * 256 + threadIdx.x;
    if (e < EE) atomicAdd(&g_deg[ei[EE + e]], 1);
}

// partial scan: grid 98 x 256, 4 elems/thread; also computes dinv
__global__ void k_scan_part() {
    __shared__ int ws[8];
    int t = threadIdx.x, b = blockIdx.x;
    int base = b * 1024 + t * 4;
    int4 d = make_int4(0, 0, 0, 0);
    if (base + 3 < NN) d = *(const int4*)&g_deg[base];
    else {
        if (base + 0 < NN) d.x = g_deg[base + 0];
        if (base + 1 < NN) d.y = g_deg[base + 1];
        if (base + 2 < NN) d.z = g_deg[base + 2];
    }
    float4 dv;
    dv.x = d.x > 0 ? rsqrtf((float)d.x) : 0.f;
    dv.y = d.y > 0 ? rsqrtf((float)d.y) : 0.f;
    dv.z = d.z > 0 ? rsqrtf((float)d.z) : 0.f;
    dv.w = d.w > 0 ? rsqrtf((float)d.w) : 0.f;
    if (base + 3 < NN) *(float4*)&g_dinv[base] = dv;
    else {
        if (base + 0 < NN) g_dinv[base + 0] = dv.x;
        if (base + 1 < NN) g_dinv[base + 1] = dv.y;
        if (base + 2 < NN) g_dinv[base + 2] = dv.z;
    }
    int s = d.x + d.y + d.z + d.w;
    int lane = t & 31, wid = t >> 5;
    int sc = s;
#pragma unroll
    for (int o = 1; o < 32; o <<= 1) {
        int u = __shfl_up_sync(0xffffffffu, sc, o);
        if (lane >= o) sc += u;
    }
    if (lane == 31) ws[wid] = sc;
    __syncthreads();
    if (t < 8) {
        int v = ws[t];
#pragma unroll
        for (int o = 1; o < 8; o <<= 1) {
            int u = __shfl_up_sync(0xffu, v, o);
            if (t >= o) v += u;
        }
        ws[t] = v;
    }
    __syncthreads();
    int excl = sc - s + (wid ? ws[wid - 1] : 0);
    int4 rp;
    rp.x = excl; rp.y = excl + d.x; rp.z = rp.y + d.y; rp.w = rp.z + d.z;
    if (base + 3 < NN) *(int4*)&g_rowptr[base] = rp;
    else {
        if (base + 0 < NN) g_rowptr[base + 0] = rp.x;
        if (base + 1 < NN) g_rowptr[base + 1] = rp.y;
        if (base + 2 < NN) g_rowptr[base + 2] = rp.z;
    }
    if (t == 255) g_bsum[b] = excl + s;
}

__global__ void k_scan_tots(int nblk) {   // 1 warp
    int lane = threadIdx.x;
    int carry = 0;
    for (int i = 0; i < 4; ++i) {
        int idx = i * 32 + lane;
        int v = idx < nblk ? g_bsum[idx] : 0;
        int sc = v;
#pragma unroll
        for (int o = 1; o < 32; o <<= 1) {
            int u = __shfl_up_sync(0xffffffffu, sc, o);
            if (lane >= o) sc += u;
        }
        if (idx < nblk) g_boff[idx] = carry + sc - v;
        carry += __shfl_sync(0xffffffffu, sc, 31);
    }
    if (lane == 0) g_rowptr[NN] = carry;
}

__global__ void k_scan_add() {
    int t = threadIdx.x, b = blockIdx.x;
    if (b == 0) return;
    int off = g_boff[b];
    int base = b * 1024 + t * 4;
    if (base + 3 < NN) {
        int4 rp = *(const int4*)&g_rowptr[base];
        rp.x += off; rp.y += off; rp.z += off; rp.w += off;
        *(int4*)&g_rowptr[base] = rp;
    } else {
        for (int i = 0; i < 4; ++i)
            if (base + i < NN) g_rowptr[base + i] += off;
    }
}

__global__ void k_fill(const int* __restrict__ ei) {
    int e = blockIdx.x * 256 + threadIdx.x;
    if (e >= EE) return;
    int r = ei[e];
    int c = ei[EE + e];
    int p = g_rowptr[c] + atomicAdd(&g_fill[c], 1);
    float v = g_dinv[r] * g_dinv[c];
    g_edge[p] = make_int2(r, __float_as_int(v));
}

// ===================== tf32 mma.sync GEMM (3xTF32 split) ====================
__device__ __forceinline__ void splitf(float x, uint32_t& h, uint32_t& l) {
    uint32_t xb = __float_as_uint(x);
    uint32_t hb = xb & 0xFFFFE000u;
    h = hb;
    l = __float_as_uint(x - __uint_as_float(hb));
}

__device__ __forceinline__ void mma8(float* d, const uint32_t* a, uint32_t b0, uint32_t b1) {
    asm volatile(
        "mma.sync.aligned.m16n8k8.row.col.f32.tf32.tf32.f32 "
        "{%0,%1,%2,%3}, {%4,%5,%6,%7}, {%8,%9}, {%0,%1,%2,%3};"
        : "+f"(d[0]), "+f"(d[1]), "+f"(d[2]), "+f"(d[3])
        : "r"(a[0]), "r"(a[1]), "r"(a[2]), "r"(a[3]), "r"(b0), "r"(b1));
}

#define GEMM_SMEM ((2 * 128 * AST + 3 * 128) * 4)

__global__ __launch_bounds__(256)
void k_gemm_mma(const float* __restrict__ A, const float* __restrict__ W,
                const float* __restrict__ bias, float* __restrict__ Z, int nrows) {
    extern __shared__ float sm[];
    float* sA    = sm;                    // [128][AST]
    float* sB    = sm + 128 * AST;        // [128][AST]
    float* sSum  = sm + 2 * 128 * AST;    // [128]
    float* sSq   = sSum + 128;            // [128]
    float* sBias = sSq + 128;             // [128]

    const int tid = threadIdx.x;
    const int wid = tid >> 5, lane = tid & 31;
    const int rowBase = blockIdx.x * 128;
    const int r = lane >> 2, c = lane & 3;

    const float4* A4 = (const float4*)A;
#pragma unroll
    for (int it = 0; it < 16; ++it) {
        int vec = tid + it * 256;
        int row = vec >> 5, q = vec & 31;
        int gr = rowBase + row;
        float4 v = make_float4(0.f, 0.f, 0.f, 0.f);
        if (gr < nrows) v = A4[(size_t)gr * 32 + q];
        *(float4*)&sA[row * AST + q * 4] = v;
    }
    const float4* W4 = (const float4*)W;
#pragma unroll
    for (int it = 0; it < 16; ++it) {
        int vec = tid + it * 256;
        int row = vec >> 5, q = vec & 31;
        float4 v = W4[vec];
        *(float4*)&sB[row * AST + q * 4] = v;
    }
    if (tid < 128) { sSum[tid] = 0.f; sSq[tid] = 0.f; sBias[tid] = bias[tid]; }
    __syncthreads();

    const int wm = wid & 3, wn = wid >> 2;
    float acc[2][8][4];
#pragma unroll
    for (int mt = 0; mt < 2; ++mt)
#pragma unroll
        for (int nt = 0; nt < 8; ++nt)
#pragma unroll
            for (int i = 0; i < 4; ++i) acc[mt][nt][i] = 0.f;

    const int aBase = (wm * 32 + r) * AST + c;
    const int bBase = (wn * 64 + r) * AST + c;

#pragma unroll 1
    for (int ks = 0; ks < 16; ++ks) {
        const int kb = ks * 8;
        uint32_t ah[2][4], al[2][4];
#pragma unroll
        for (int mt = 0; mt < 2; ++mt) {
            int ba = aBase + mt * 16 * AST + kb;
            splitf(sA[ba],               ah[mt][0], al[mt][0]);
            splitf(sA[ba + 8 * AST],     ah[mt][1], al[mt][1]);
            splitf(sA[ba + 4],           ah[mt][2], al[mt][2]);
            splitf(sA[ba + 8 * AST + 4], ah[mt][3], al[mt][3]);
        }
#pragma unroll
        for (int nt = 0; nt < 8; ++nt) {
            int bb = bBase + nt * 8 * AST + kb;
            uint32_t bh0, bl0, bh1, bl1;
            splitf(sB[bb],     bh0, bl0);
            splitf(sB[bb + 4], bh1, bl1);
#pragma unroll
            for (int mt = 0; mt < 2; ++mt) {
                mma8(acc[mt][nt], ah[mt], bh0, bh1);
                mma8(acc[mt][nt], ah[mt], bl0, bl1);
                mma8(acc[mt][nt], al[mt], bh0, bh1);
            }
        }
    }

    float cs[16], cq[16];
#pragma unroll
    for (int i = 0; i < 16; ++i) { cs[i] = 0.f; cq[i] = 0.f; }

#pragma unroll
    for (int nt = 0; nt < 8; ++nt) {
        int C0 = wn * 64 + nt * 8 + 2 * c;
        float b0 = sBias[C0], b1 = sBias[C0 + 1];
#pragma unroll
        for (int mt = 0; mt < 2; ++mt) {
            int R0 = rowBase + wm * 32 + mt * 16 + r;
            int R1 = R0 + 8;
            if (R0 < nrows) {
                float z0 = acc[mt][nt][0] + b0;
                float z1 = acc[mt][nt][1] + b1;
                *(float2*)&Z[(size_t)R0 * 128 + C0] = make_float2(z0, z1);
                cs[2 * nt] += z0; cq[2 * nt] += z0 * z0;
                cs[2 * nt + 1] += z1; cq[2 * nt + 1] += z1 * z1;
            }
            if (R1 < nrows) {
                float z2 = acc[mt][nt][2] + b0;
                float z3 = acc[mt][nt][3] + b1;
                *(float2*)&Z[(size_t)R1 * 128 + C0] = make_float2(z2, z3);
                cs[2 * nt] += z2; cq[2 * nt] += z2 * z2;
                cs[2 * nt + 1] += z3; cq[2 * nt + 1] += z3 * z3;
            }
        }
    }
#pragma unroll
    for (int o = 4; o <= 16; o <<= 1) {
#pragma unroll
        for (int i = 0; i < 16; ++i) {
            cs[i] += __shfl_xor_sync(0xffffffffu, cs[i], o);
            cq[i] += __shfl_xor_sync(0xffffffffu, cq[i], o);
        }
    }
    if (r == 0) {
#pragma unroll
        for (int nt = 0; nt < 8; ++nt) {
            int C0 = wn * 64 + nt * 8 + 2 * c;
            atomicAdd(&sSum[C0],     cs[2 * nt]);
            atomicAdd(&sSum[C0 + 1], cs[2 * nt + 1]);
            atomicAdd(&sSq[C0],      cq[2 * nt]);
            atomicAdd(&sSq[C0 + 1],  cq[2 * nt + 1]);
        }
    }
    __syncthreads();
    if (tid < 128) {
        atomicAdd(&g_stats[tid], sSum[tid]);
        atomicAdd(&g_stats[128 + tid], sSq[tid]);
    }
}

// ========== BN prep (reads stats, then re-zeroes them for next GEMM) =======
__global__ void k_bnprep(const float* __restrict__ gamma, const float* __restrict__ beta) {
    int j = threadIdx.x;
    if (j < DH) {
        float s = g_stats[j];
        float q = g_stats[128 + j];
        float mu = s * (1.0f / (float)NN);
        float var = q * (1.0f / (float)NN) - mu * mu;
        float rs = rsqrtf(var + BN_EPS);
        float sc = gamma[j] * rs;
        g_scale[j] = sc;
        g_shift[j] = beta[j] - mu * sc;
        g_stats[j] = 0.f;
        g_stats[128 + j] = 0.f;
    }
}

// ========== fused BN/ReLU/residual; optional fp32 + fp16 outputs ===========
__global__ void k_bnfused(const float4* __restrict__ Z, const float4* __restrict__ X0,
                          float4* __restrict__ OutF, uint2* __restrict__ OutH, int nvec) {
    int i = blockIdx.x * 256 + threadIdx.x;
    if (i >= nvec) return;
    int c4 = i & 31;
    float4 sc = ((const float4*)g_scale)[c4];
    float4 sh = ((const float4*)g_shift)[c4];
    float4 z = Z[i];
    float4 h;
    h.x = fmaxf(fmaf(z.x, sc.x, sh.x), 0.f);
    h.y = fmaxf(fmaf(z.y, sc.y, sh.y), 0.f);
    h.z = fmaxf(fmaf(z.z, sc.z, sh.z), 0.f);
    h.w = fmaxf(fmaf(z.w, sc.w, sh.w), 0.f);
    if (X0) {
        float4 x0 = X0[i];
        h.x += x0.x; h.y += x0.y; h.z += x0.z; h.w += x0.w;
    }
    if (OutF) OutF[i] = h;
    if (OutH) {
        __half2 p0 = __floats2half2_rn(h.x, h.y);
        __half2 p1 = __floats2half2_rn(h.z, h.w);
        uint2 u;
        u.x = *(uint32_t*)&p0;
        u.y = *(uint32_t*)&p1;
        OutH[i] = u;
    }
}

// ===================== SPMM (warp/node, fp16 gather, fp32 accumulate) =======
__global__ void k_spmm(const uint2* __restrict__ H, float4* __restrict__ O) {
    int gt = blockIdx.x * 256 + threadIdx.x;
    int w = gt >> 5;
    int lane = gt & 31;
    if (w >= NN) return;
    int rp0 = g_rowptr[w], rp1 = g_rowptr[w + 1];
    float4 acc = make_float4(0.f, 0.f, 0.f, 0.f);
    for (int base = rp0; base < rp1; base += 32) {
        int nb = min(32, rp1 - base);
        int s = 0; float v = 0.f;
        if (lane < nb) {
            int2 e = g_edge[base + lane];
            s = e.x; v = __int_as_float(e.y);
        }
        for (int j = 0; j < nb; ++j) {
            int sj = __shfl_sync(0xffffffffu, s, j);
            float vj = __shfl_sync(0xffffffffu, v, j);
            uint2 u = H[(size_t)sj * 32 + lane];
            float2 f0 = __half22float2(*(__half2*)&u.x);
            float2 f1 = __half22float2(*(__half2*)&u.y);
            acc.x = fmaf(vj, f0.x, acc.x);
            acc.y = fmaf(vj, f0.y, acc.y);
            acc.z = fmaf(vj, f1.x, acc.z);
            acc.w = fmaf(vj, f1.y, acc.w);
        }
    }
    O[(size_t)w * 32 + lane] = acc;
}

// ===================== classifier (N x 40, fp32) ============================
__global__ void k_cls(const float* __restrict__ A, const float* __restrict__ W,
                      const float* __restrict__ bias, float* __restrict__ O, int nrows) {
    extern __shared__ float sm[];
    float* As = sm;             // [128][128]
    float* Wt = sm + 16384;     // [128][40]
    const int tx = threadIdx.x, ty = threadIdx.y;
    const int tid = ty * 8 + tx;
    const int rowBase = blockIdx.x * 128;

    for (int idx = tid; idx < DOUT * DH; idx += 128) {
        int j = idx >> 7, k = idx & 127;
        Wt[k * DOUT + j] = W[idx];
    }
    const float4* A4 = (const float4*)A;
#pragma unroll
    for (int it = 0; it < 32; ++it) {
        int vec = tid + it * 128;
        int rr = vec >> 5, k4 = vec & 31;
        int grow = rowBase + rr;
        float4 a = make_float4(0.f, 0.f, 0.f, 0.f);
        if (grow < nrows) a = A4[(size_t)grow * 32 + k4];
        *(float4*)(As + rr * 128 + k4 * 4) = a;
    }
    __syncthreads();

    const int r0 = ty * 8, c0 = tx * 5;
    float acc[8][5];
#pragma unroll
    for (int r = 0; r < 8; ++r)
#pragma unroll
        for (int c = 0; c < 5; ++c) acc[r][c] = 0.f;

#pragma unroll 4
    for (int k = 0; k < 128; ++k) {
        float b[5];
#pragma unroll
        for (int c = 0; c < 5; ++c) b[c] = Wt[k * DOUT + c0 + c];
#pragma unroll
        for (int r = 0; r < 8; ++r) {
            float a = As[(r0 + r) * 128 + k];
#pragma unroll
            for (int c = 0; c < 5; ++c) acc[r][c] = fmaf(a, b[c], acc[r][c]);
        }
    }
    float bb[5];
#pragma unroll
    for (int c = 0; c < 5; ++c) bb[c] = bias[c0 + c];
#pragma unroll
    for (int r = 0; r < 8; ++r) {
        int grow = rowBase + r0 + r;
        if (grow < nrows) {
#pragma unroll
            for (int c = 0; c < 5; ++c)
                O[(size_t)grow * DOUT + c0 + c] = acc[r][c] + bb[c];
        }
    }
}

// ===================== driver ===============================================
extern "C" void kernel_launch(void* const* d_in, const int* in_sizes, int n_in,
                              void* d_out, int out_size) {
    const float* x      = (const float*)d_in[0];
    const int*   ei     = (const int*)d_in[1];
    const float* fc_w   = (const float*)d_in[2];
    const float* fc_b   = (const float*)d_in[3];
    const float* conv_w = (const float*)d_in[4];
    const float* conv_b = (const float*)d_in[5];
    const float* gamma  = (const float*)d_in[6];
    const float* beta   = (const float*)d_in[7];
    const float* cls_w  = (const float*)d_in[8];
    const float* cls_b  = (const float*)d_in[9];
    float* out = (float*)d_out;

    float *h0f, *bA, *bB;
    __half* hH;
    cudaGetSymbolAddress((void**)&h0f, g_h0f);
    cudaGetSymbolAddress((void**)&bA, g_bA);
    cudaGetSymbolAddress((void**)&bB, g_bB);
    cudaGetSymbolAddress((void**)&hH, g_hH);

    const int CLS_SMEM = 128 * 128 * 4 + DH * DOUT * 4;
    cudaFuncSetAttribute(k_gemm_mma, cudaFuncAttributeMaxDynamicSharedMemorySize, GEMM_SMEM);
    cudaFuncSetAttribute(k_cls,      cudaFuncAttributeMaxDynamicSharedMemorySize, CLS_SMEM);

    const int nodeBlocks = (NN + 255) / 256;
    const int edgeBlocks = (EE + 255) / 256;
    const int scanBlocks = (NN + 1023) / 1024;  // 98
    const int gemmGrid   = (NN + 127) / 128;    // 782
    const int vecBlocks  = (NN * 32) / 256;     // 12500

    // graph build
    k_zero_build<<<nodeBlocks, 256>>>();
    k_degree<<<edgeBlocks, 256>>>(ei);
    k_scan_part<<<scanBlocks, 256>>>();
    k_scan_tots<<<1, 32>>>(scanBlocks);
    k_scan_add<<<scanBlocks, 256>>>();
    k_fill<<<edgeBlocks, 256>>>(ei);

    // layer 0: fc -> bn0 -> relu ; write x0 fp32 + h fp16
    k_gemm_mma<<<gemmGrid, 256, GEMM_SMEM>>>(x, fc_w, fc_b, bB, NN);
    k_bnprep<<<1, 128>>>(gamma, beta);
    k_bnfused<<<vecBlocks, 256>>>((const float4*)bB, (const float4*)0,
                                  (float4*)h0f, (uint2*)hH, NN * 32);

    for (int i = 0; i < 3; ++i) {
        k_spmm<<<vecBlocks, 256>>>((const uint2*)hH, (float4*)bA);
        k_gemm_mma<<<gemmGrid, 256, GEMM_SMEM>>>(bA, conv_w + i * DH * DH,
                                                 conv_b + i * DH, bB, NN);
        k_bnprep<<<1, 128>>>(gamma + (i + 1) * DH, beta + (i + 1) * DH);
        if (i < 2) {
            // h (fp16) for next SPMM
            k_bnfused<<<vecBlocks, 256>>>((const float4*)bB, (const float4*)h0f,
                                          (float4*)0, (uint2*)hH, NN * 32);
        } else {
            // final h3 fp32 for classifier
            k_bnfused<<<vecBlocks, 256>>>((const float4*)bB, (const float4*)h0f,
                                          (float4*)bA, (uint2*)0, NN * 32);
        }
    }

    k_cls<<<gemmGrid, dim3(8, 16), CLS_SMEM>>>(bA, cls_w, cls_b, out, NN);
}

// round 5
// speedup vs baseline: 1.8401x; 1.1926x over previous
#include <cuda_runtime.h>
#include <cuda_fp16.h>
#include <cstdint>

#define NN 100000
#define EE 1600000
#define DH 128
#define DOUT 40
#define BN_EPS 1e-5f
#define HST 68   // half2 stride per row in GEMM smem (4B units), conflict-free

// ===================== scratch ==============================================
__device__ __half g_x0h[NN * DH];   // x0 residual, fp16 (== fp16 h0)
__device__ __half g_hH[NN * DH];    // current h for SPMM gather (fp16)
__device__ float  g_bA[NN * DH];    // agg (and final h3)
__device__ float  g_bB[NN * DH];    // z = GEMM output
__device__ int    g_deg[NN];
__device__ int    g_fill[NN];
__device__ float  g_dinv[NN];
__device__ int    g_rowptr[NN + 1];
__device__ int2   g_edge[EE];       // {src, float bits of val}
__device__ int    g_bsum[128];
__device__ int    g_boff[128];
__device__ float  g_stats[2 * DH];
__device__ float  g_scale[DH];
__device__ float  g_shift[DH];

// ===================== graph build ==========================================
__global__ void k_zero_build() {
    int i = blockIdx.x * 256 + threadIdx.x;
    if (i < NN) { g_deg[i] = 0; g_fill[i] = 0; }
}

__global__ void k_degree(const int* __restrict__ ei) {
    int e = blockIdx.x * 256 + threadIdx.x;
    if (e < EE) atomicAdd(&g_deg[ei[EE + e]], 1);
}

__global__ void k_scan_part() {
    __shared__ int ws[8];
    int t = threadIdx.x, b = blockIdx.x;
    int base = b * 1024 + t * 4;
    int4 d = make_int4(0, 0, 0, 0);
    if (base + 3 < NN) d = *(const int4*)&g_deg[base];
    else {
        if (base + 0 < NN) d.x = g_deg[base + 0];
        if (base + 1 < NN) d.y = g_deg[base + 1];
        if (base + 2 < NN) d.z = g_deg[base + 2];
    }
    float4 dv;
    dv.x = d.x > 0 ? rsqrtf((float)d.x) : 0.f;
    dv.y = d.y > 0 ? rsqrtf((float)d.y) : 0.f;
    dv.z = d.z > 0 ? rsqrtf((float)d.z) : 0.f;
    dv.w = d.w > 0 ? rsqrtf((float)d.w) : 0.f;
    if (base + 3 < NN) *(float4*)&g_dinv[base] = dv;
    else {
        if (base + 0 < NN) g_dinv[base + 0] = dv.x;
        if (base + 1 < NN) g_dinv[base + 1] = dv.y;
        if (base + 2 < NN) g_dinv[base + 2] = dv.z;
    }
    int s = d.x + d.y + d.z + d.w;
    int lane = t & 31, wid = t >> 5;
    int sc = s;
#pragma unroll
    for (int o = 1; o < 32; o <<= 1) {
        int u = __shfl_up_sync(0xffffffffu, sc, o);
        if (lane >= o) sc += u;
    }
    if (lane == 31) ws[wid] = sc;
    __syncthreads();
    if (t < 8) {
        int v = ws[t];
#pragma unroll
        for (int o = 1; o < 8; o <<= 1) {
            int u = __shfl_up_sync(0xffu, v, o);
            if (t >= o) v += u;
        }
        ws[t] = v;
    }
    __syncthreads();
    int excl = sc - s + (wid ? ws[wid - 1] : 0);
    int4 rp;
    rp.x = excl; rp.y = excl + d.x; rp.z = rp.y + d.y; rp.w = rp.z + d.z;
    if (base + 3 < NN) *(int4*)&g_rowptr[base] = rp;
    else {
        if (base + 0 < NN) g_rowptr[base + 0] = rp.x;
        if (base + 1 < NN) g_rowptr[base + 1] = rp.y;
        if (base + 2 < NN) g_rowptr[base + 2] = rp.z;
    }
    if (t == 255) g_bsum[b] = excl + s;
}

__global__ void k_scan_tots(int nblk) {
    int lane = threadIdx.x;
    int carry = 0;
    for (int i = 0; i < 4; ++i) {
        int idx = i * 32 + lane;
        int v = idx < nblk ? g_bsum[idx] : 0;
        int sc = v;
#pragma unroll
        for (int o = 1; o < 32; o <<= 1) {
            int u = __shfl_up_sync(0xffffffffu, sc, o);
            if (lane >= o) sc += u;
        }
        if (idx < nblk) g_boff[idx] = carry + sc - v;
        carry += __shfl_sync(0xffffffffu, sc, 31);
    }
    if (lane == 0) g_rowptr[NN] = carry;
}

__global__ void k_scan_add() {
    int t = threadIdx.x, b = blockIdx.x;
    if (b == 0) return;
    int off = g_boff[b];
    int base = b * 1024 + t * 4;
    if (base + 3 < NN) {
        int4 rp = *(const int4*)&g_rowptr[base];
        rp.x += off; rp.y += off; rp.z += off; rp.w += off;
        *(int4*)&g_rowptr[base] = rp;
    } else {
        for (int i = 0; i < 4; ++i)
            if (base + i < NN) g_rowptr[base + i] += off;
    }
}

__global__ void k_fill(const int* __restrict__ ei) {
    int e = blockIdx.x * 256 + threadIdx.x;
    if (e >= EE) return;
    int r = ei[e];
    int c = ei[EE + e];
    int p = g_rowptr[c] + atomicAdd(&g_fill[c], 1);
    float v = g_dinv[r] * g_dinv[c];
    g_edge[p] = make_int2(r, __float_as_int(v));
}

// ===================== split-fp16 mma.sync GEMM =============================
// Z = A @ W^T + b, BN stats epilogue. A,W split x=xh+xl (fp16 pair) once at
// smem load; mainloop: mma m16n8k16 f16 products hh + hl + lh (fp32 accum).
// tile 128x128xK128, 8 warps (4m x 2n), warp tile 32x64.

__device__ __forceinline__ void split_h2(float x, float y, uint32_t& hi, uint32_t& lo) {
    __half2 h = __floats2half2_rn(x, y);
    float2 hf = __half22float2(h);
    __half2 l = __floats2half2_rn(x - hf.x, y - hf.y);
    hi = *(uint32_t*)&h;
    lo = *(uint32_t*)&l;
}

__device__ __forceinline__ void mma16(float* d, const uint32_t* a, uint32_t b0, uint32_t b1) {
    asm volatile(
        "mma.sync.aligned.m16n8k16.row.col.f32.f16.f16.f32 "
        "{%0,%1,%2,%3}, {%4,%5,%6,%7}, {%8,%9}, {%0,%1,%2,%3};"
        : "+f"(d[0]), "+f"(d[1]), "+f"(d[2]), "+f"(d[3])
        : "r"(a[0]), "r"(a[1]), "r"(a[2]), "r"(a[3]), "r"(b0), "r"(b1));
}

#define GEMM_SMEM (4 * 128 * HST * 4 + 3 * 128 * 4)

__global__ __launch_bounds__(256)
void k_gemm_mma(const float* __restrict__ A, const float* __restrict__ W,
                const float* __restrict__ bias, float* __restrict__ Z, int nrows) {
    extern __shared__ uint32_t smu[];
    uint32_t* sAh = smu;                    // [128][HST] half2 units
    uint32_t* sAl = smu + 128 * HST;
    uint32_t* sBh = smu + 2 * 128 * HST;
    uint32_t* sBl = smu + 3 * 128 * HST;
    float* sSum  = (float*)(smu + 4 * 128 * HST);
    float* sSq   = sSum + 128;
    float* sBias = sSq + 128;

    const int tid = threadIdx.x;
    const int wid = tid >> 5, lane = tid & 31;
    const int rowBase = blockIdx.x * 128;
    const int r = lane >> 2, c = lane & 3;

    const float4* A4 = (const float4*)A;
#pragma unroll
    for (int it = 0; it < 16; ++it) {
        int vec = tid + it * 256;
        int row = vec >> 5, q = vec & 31;   // q: float4 index = k/4
        int gr = rowBase + row;
        float4 v = make_float4(0.f, 0.f, 0.f, 0.f);
        if (gr < nrows) v = A4[(size_t)gr * 32 + q];
        uint32_t h0, l0, h1, l1;
        split_h2(v.x, v.y, h0, l0);
        split_h2(v.z, v.w, h1, l1);
        int idx = row * HST + 2 * q;
        *(uint2*)&sAh[idx] = make_uint2(h0, h1);
        *(uint2*)&sAl[idx] = make_uint2(l0, l1);
    }
    const float4* W4 = (const float4*)W;
#pragma unroll
    for (int it = 0; it < 16; ++it) {
        int vec = tid + it * 256;
        int row = vec >> 5, q = vec & 31;
        float4 v = W4[vec];
        uint32_t h0, l0, h1, l1;
        split_h2(v.x, v.y, h0, l0);
        split_h2(v.z, v.w, h1, l1);
        int idx = row * HST + 2 * q;
        *(uint2*)&sBh[idx] = make_uint2(h0, h1);
        *(uint2*)&sBl[idx] = make_uint2(l0, l1);
    }
    if (tid < 128) { sSum[tid] = 0.f; sSq[tid] = 0.f; sBias[tid] = bias[tid]; }
    __syncthreads();

    const int wm = wid & 3, wn = wid >> 2;
    float acc[2][8][4];
#pragma unroll
    for (int mt = 0; mt < 2; ++mt)
#pragma unroll
        for (int nt = 0; nt < 8; ++nt)
#pragma unroll
            for (int i = 0; i < 4; ++i) acc[mt][nt][i] = 0.f;

#pragma unroll 1
    for (int ks = 0; ks < 8; ++ks) {        // K=16 per step
        const int kb = ks * 8 + c;
        uint32_t ah[2][4], al[2][4];
#pragma unroll
        for (int mt = 0; mt < 2; ++mt) {
            int ba = (wm * 32 + mt * 16 + r) * HST + kb;
            ah[mt][0] = sAh[ba];
            ah[mt][1] = sAh[ba + 8 * HST];
            ah[mt][2] = sAh[ba + 4];
            ah[mt][3] = sAh[ba + 8 * HST + 4];
            al[mt][0] = sAl[ba];
            al[mt][1] = sAl[ba + 8 * HST];
            al[mt][2] = sAl[ba + 4];
            al[mt][3] = sAl[ba + 8 * HST + 4];
        }
#pragma unroll
        for (int nt = 0; nt < 8; ++nt) {
            int bb = (wn * 64 + nt * 8 + r) * HST + kb;
            uint32_t bh0 = sBh[bb], bh1 = sBh[bb + 4];
            uint32_t bl0 = sBl[bb], bl1 = sBl[bb + 4];
#pragma unroll
            for (int mt = 0; mt < 2; ++mt) {
                mma16(acc[mt][nt], ah[mt], bh0, bh1);
                mma16(acc[mt][nt], ah[mt], bl0, bl1);
                mma16(acc[mt][nt], al[mt], bh0, bh1);
            }
        }
    }

    // epilogue: bias add, store, BN stats
    float cs[16], cq[16];
#pragma unroll
    for (int i = 0; i < 16; ++i) { cs[i] = 0.f; cq[i] = 0.f; }

#pragma unroll
    for (int nt = 0; nt < 8; ++nt) {
        int C0 = wn * 64 + nt * 8 + 2 * c;
        float b0 = sBias[C0], b1 = sBias[C0 + 1];
#pragma unroll
        for (int mt = 0; mt < 2; ++mt) {
            int R0 = rowBase + wm * 32 + mt * 16 + r;
            int R1 = R0 + 8;
            if (R0 < nrows) {
                float z0 = acc[mt][nt][0] + b0;
                float z1 = acc[mt][nt][1] + b1;
                *(float2*)&Z[(size_t)R0 * 128 + C0] = make_float2(z0, z1);
                cs[2 * nt] += z0; cq[2 * nt] += z0 * z0;
                cs[2 * nt + 1] += z1; cq[2 * nt + 1] += z1 * z1;
            }
            if (R1 < nrows) {
                float z2 = acc[mt][nt][2] + b0;
                float z3 = acc[mt][nt][3] + b1;
                *(float2*)&Z[(size_t)R1 * 128 + C0] = make_float2(z2, z3);
                cs[2 * nt] += z2; cq[2 * nt] += z2 * z2;
                cs[2 * nt + 1] += z3; cq[2 * nt + 1] += z3 * z3;
            }
        }
    }
#pragma unroll
    for (int o = 4; o <= 16; o <<= 1) {
#pragma unroll
        for (int i = 0; i < 16; ++i) {
            cs[i] += __shfl_xor_sync(0xffffffffu, cs[i], o);
            cq[i] += __shfl_xor_sync(0xffffffffu, cq[i], o);
        }
    }
    if (r == 0) {
#pragma unroll
        for (int nt = 0; nt < 8; ++nt) {
            int C0 = wn * 64 + nt * 8 + 2 * c;
            atomicAdd(&sSum[C0],     cs[2 * nt]);
            atomicAdd(&sSum[C0 + 1], cs[2 * nt + 1]);
            atomicAdd(&sSq[C0],      cq[2 * nt]);
            atomicAdd(&sSq[C0 + 1],  cq[2 * nt + 1]);
        }
    }
    __syncthreads();
    if (tid < 128) {
        atomicAdd(&g_stats[tid], sSum[tid]);
        atomicAdd(&g_stats[128 + tid], sSq[tid]);
    }
}

// ========== BN prep (reads stats, then re-zeroes for next GEMM) ============
__global__ void k_bnprep(const float* __restrict__ gamma, const float* __restrict__ beta) {
    int j = threadIdx.x;
    if (j < DH) {
        float s = g_stats[j];
        float q = g_stats[128 + j];
        float mu = s * (1.0f / (float)NN);
        float var = q * (1.0f / (float)NN) - mu * mu;
        float rs = rsqrtf(var + BN_EPS);
        float sc = gamma[j] * rs;
        g_scale[j] = sc;
        g_shift[j] = beta[j] - mu * sc;
        g_stats[j] = 0.f;
        g_stats[128 + j] = 0.f;
    }
}

// ========== fused BN/ReLU/residual; fp16 residual input =====================
__global__ void k_bnfused(const float4* __restrict__ Z, const uint2* __restrict__ X0,
                          float4* __restrict__ OutF, uint2* __restrict__ OutH, int nvec) {
    int i = blockIdx.x * 256 + threadIdx.x;
    if (i >= nvec) return;
    int c4 = i & 31;
    float4 sc = ((const float4*)g_scale)[c4];
    float4 sh = ((const float4*)g_shift)[c4];
    float4 z = Z[i];
    float4 h;
    h.x = fmaxf(fmaf(z.x, sc.x, sh.x), 0.f);
    h.y = fmaxf(fmaf(z.y, sc.y, sh.y), 0.f);
    h.z = fmaxf(fmaf(z.z, sc.z, sh.z), 0.f);
    h.w = fmaxf(fmaf(z.w, sc.w, sh.w), 0.f);
    if (X0) {
        uint2 u = X0[i];
        float2 x0 = __half22float2(*(__half2*)&u.x);
        float2 x1 = __half22float2(*(__half2*)&u.y);
        h.x += x0.x; h.y += x0.y; h.z += x1.x; h.w += x1.y;
    }
    if (OutF) OutF[i] = h;
    if (OutH) {
        __half2 p0 = __floats2half2_rn(h.x, h.y);
        __half2 p1 = __floats2half2_rn(h.z, h.w);
        uint2 u;
        u.x = *(uint32_t*)&p0;
        u.y = *(uint32_t*)&p1;
        OutH[i] = u;
    }
}

// ===================== SPMM (warp/node, fp16 gather, fp32 accumulate) =======
__global__ void k_spmm(const uint2* __restrict__ H, float4* __restrict__ O) {
    int gt = blockIdx.x * 256 + threadIdx.x;
    int w = gt >> 5;
    int lane = gt & 31;
    if (w >= NN) return;
    int rp0 = g_rowptr[w], rp1 = g_rowptr[w + 1];
    float4 acc = make_float4(0.f, 0.f, 0.f, 0.f);
    for (int base = rp0; base < rp1; base += 32) {
        int nb = min(32, rp1 - base);
        int s = 0; float v = 0.f;
        if (lane < nb) {
            int2 e = g_edge[base + lane];
            s = e.x; v = __int_as_float(e.y);
        }
        for (int j = 0; j < nb; ++j) {
            int sj = __shfl_sync(0xffffffffu, s, j);
            float vj = __shfl_sync(0xffffffffu, v, j);
            uint2 u = H[(size_t)sj * 32 + lane];
            float2 f0 = __half22float2(*(__half2*)&u.x);
            float2 f1 = __half22float2(*(__half2*)&u.y);
            acc.x = fmaf(vj, f0.x, acc.x);
            acc.y = fmaf(vj, f0.y, acc.y);
            acc.z = fmaf(vj, f1.x, acc.z);
            acc.w = fmaf(vj, f1.y, acc.w);
        }
    }
    O[(size_t)w * 32 + lane] = acc;
}

// ===================== classifier (N x 40, fp32) ============================
__global__ void k_cls(const float* __restrict__ A, const float* __restrict__ W,
                      const float* __restrict__ bias, float* __restrict__ O, int nrows) {
    extern __shared__ float sm[];
    float* As = sm;             // [128][128]
    float* Wt = sm + 16384;     // [128][40]
    const int tx = threadIdx.x, ty = threadIdx.y;
    const int tid = ty * 8 + tx;
    const int rowBase = blockIdx.x * 128;

    for (int idx = tid; idx < DOUT * DH; idx += 128) {
        int j = idx >> 7, k = idx & 127;
        Wt[k * DOUT + j] = W[idx];
    }
    const float4* A4 = (const float4*)A;
#pragma unroll
    for (int it = 0; it < 32; ++it) {
        int vec = tid + it * 128;
        int rr = vec >> 5, k4 = vec & 31;
        int grow = rowBase + rr;
        float4 a = make_float4(0.f, 0.f, 0.f, 0.f);
        if (grow < nrows) a = A4[(size_t)grow * 32 + k4];
        *(float4*)(As + rr * 128 + k4 * 4) = a;
    }
    __syncthreads();

    const int r0 = ty * 8, c0 = tx * 5;
    float acc[8][5];
#pragma unroll
    for (int r = 0; r < 8; ++r)
#pragma unroll
        for (int c = 0; c < 5; ++c) acc[r][c] = 0.f;

#pragma unroll 4
    for (int k = 0; k < 128; ++k) {
        float b[5];
#pragma unroll
        for (int c = 0; c < 5; ++c) b[c] = Wt[k * DOUT + c0 + c];
#pragma unroll
        for (int r = 0; r < 8; ++r) {
            float a = As[(r0 + r) * 128 + k];
#pragma unroll
            for (int c = 0; c < 5; ++c) acc[r][c] = fmaf(a, b[c], acc[r][c]);
        }
    }
    float bb[5];
#pragma unroll
    for (int c = 0; c < 5; ++c) bb[c] = bias[c0 + c];
#pragma unroll
    for (int r = 0; r < 8; ++r) {
        int grow = rowBase + r0 + r;
        if (grow < nrows) {
#pragma unroll
            for (int c = 0; c < 5; ++c)
                O[(size_t)grow * DOUT + c0 + c] = acc[r][c] + bb[c];
        }
    }
}

// ===================== driver ===============================================
extern "C" void kernel_launch(void* const* d_in, const int* in_sizes, int n_in,
                              void* d_out, int out_size) {
    const float* x      = (const float*)d_in[0];
    const int*   ei     = (const int*)d_in[1];
    const float* fc_w   = (const float*)d_in[2];
    const float* fc_b   = (const float*)d_in[3];
    const float* conv_w = (const float*)d_in[4];
    const float* conv_b = (const float*)d_in[5];
    const float* gamma  = (const float*)d_in[6];
    const float* beta   = (const float*)d_in[7];
    const float* cls_w  = (const float*)d_in[8];
    const float* cls_b  = (const float*)d_in[9];
    float* out = (float*)d_out;

    float *bA, *bB;
    __half *hH, *x0h;
    cudaGetSymbolAddress((void**)&bA, g_bA);
    cudaGetSymbolAddress((void**)&bB, g_bB);
    cudaGetSymbolAddress((void**)&hH, g_hH);
    cudaGetSymbolAddress((void**)&x0h, g_x0h);

    const int CLS_SMEM = 128 * 128 * 4 + DH * DOUT * 4;
    cudaFuncSetAttribute(k_gemm_mma, cudaFuncAttributeMaxDynamicSharedMemorySize, GEMM_SMEM);
    cudaFuncSetAttribute(k_cls,      cudaFuncAttributeMaxDynamicSharedMemorySize, CLS_SMEM);

    const int nodeBlocks = (NN + 255) / 256;
    const int edgeBlocks = (EE + 255) / 256;
    const int scanBlocks = (NN + 1023) / 1024;  // 98
    const int gemmGrid   = (NN + 127) / 128;    // 782
    const int vecBlocks  = (NN * 32) / 256;     // 12500

    // graph build
    k_zero_build<<<nodeBlocks, 256>>>();
    k_degree<<<edgeBlocks, 256>>>(ei);
    k_scan_part<<<scanBlocks, 256>>>();
    k_scan_tots<<<1, 32>>>(scanBlocks);
    k_scan_add<<<scanBlocks, 256>>>();
    k_fill<<<edgeBlocks, 256>>>(ei);

    // layer 0: fc -> bn0 -> relu ; x0 (fp16) doubles as h0 for SPMM1
    k_gemm_mma<<<gemmGrid, 256, GEMM_SMEM>>>(x, fc_w, fc_b, bB, NN);
    k_bnprep<<<1, 128>>>(gamma, beta);
    k_bnfused<<<vecBlocks, 256>>>((const float4*)bB, (const uint2*)0,
                                  (float4*)0, (uint2*)x0h, NN * 32);

    for (int i = 0; i < 3; ++i) {
        const __half* hin = (i == 0) ? x0h : hH;
        k_spmm<<<vecBlocks, 256>>>((const uint2*)hin, (float4*)bA);
        k_gemm_mma<<<gemmGrid, 256, GEMM_SMEM>>>(bA, conv_w + i * DH * DH,
                                                 conv_b + i * DH, bB, NN);
        k_bnprep<<<1, 128>>>(gamma + (i + 1) * DH, beta + (i + 1) * DH);
        if (i < 2) {
            k_bnfused<<<vecBlocks, 256>>>((const float4*)bB, (const uint2*)x0h,
                                          (float4*)0, (uint2*)hH, NN * 32);
        } else {
            k_bnfused<<<vecBlocks, 256>>>((const float4*)bB, (const uint2*)x0h,
                                          (float4*)bA, (uint2*)0, NN * 32);
        }
    }

    k_cls<<<gemmGrid, dim3(8, 16), CLS_SMEM>>>(bA, cls_w, cls_b, out, NN);
}

// round 6
// speedup vs baseline: 2.2572x; 1.2267x over previous
#include <cuda_runtime.h>
#include <cuda_fp16.h>
#include <cstdint>

#define NN 100000
#define EE 1600000
#define DH 128
#define DOUT 40
#define BN_EPS 1e-5f
#define HST 68   // half2 stride per row in GEMM smem (4B units), conflict-free

// ===================== scratch ==============================================
__device__ __half g_x0h[NN * DH];   // x0 residual, fp16 (== fp16 h0)
__device__ __half g_hH[NN * DH];    // current h for SPMM gather (fp16)
__device__ __half g_aggH[NN * DH];  // SPMM output (fp16) -> GEMM A
__device__ float  g_bA[NN * DH];    // final h3 (fp32, for classifier)
__device__ float  g_bB[NN * DH];    // z = GEMM output
__device__ int    g_deg[NN];
__device__ int    g_fill[NN];
__device__ float  g_dinv[NN];
__device__ int    g_rowptr[NN + 1];
__device__ int2   g_edge[EE];       // {src, float bits of val}
__device__ int    g_bsum[128];
__device__ int    g_boff[128];
__device__ float  g_stats[2 * DH];
__device__ float  g_scale[DH];
__device__ float  g_shift[DH];

// ===================== graph build ==========================================
__global__ void k_zero_build() {
    int i = blockIdx.x * 256 + threadIdx.x;
    if (i < NN) { g_deg[i] = 0; g_fill[i] = 0; }
}

__global__ void k_degree(const int* __restrict__ ei) {
    int e = blockIdx.x * 256 + threadIdx.x;
    if (e < EE) atomicAdd(&g_deg[ei[EE + e]], 1);
}

__global__ void k_scan_part() {
    __shared__ int ws[8];
    int t = threadIdx.x, b = blockIdx.x;
    int base = b * 1024 + t * 4;
    int4 d = make_int4(0, 0, 0, 0);
    if (base + 3 < NN) d = *(const int4*)&g_deg[base];
    else {
        if (base + 0 < NN) d.x = g_deg[base + 0];
        if (base + 1 < NN) d.y = g_deg[base + 1];
        if (base + 2 < NN) d.z = g_deg[base + 2];
    }
    float4 dv;
    dv.x = d.x > 0 ? rsqrtf((float)d.x) : 0.f;
    dv.y = d.y > 0 ? rsqrtf((float)d.y) : 0.f;
    dv.z = d.z > 0 ? rsqrtf((float)d.z) : 0.f;
    dv.w = d.w > 0 ? rsqrtf((float)d.w) : 0.f;
    if (base + 3 < NN) *(float4*)&g_dinv[base] = dv;
    else {
        if (base + 0 < NN) g_dinv[base + 0] = dv.x;
        if (base + 1 < NN) g_dinv[base + 1] = dv.y;
        if (base + 2 < NN) g_dinv[base + 2] = dv.z;
    }
    int s = d.x + d.y + d.z + d.w;
    int lane = t & 31, wid = t >> 5;
    int sc = s;
#pragma unroll
    for (int o = 1; o < 32; o <<= 1) {
        int u = __shfl_up_sync(0xffffffffu, sc, o);
        if (lane >= o) sc += u;
    }
    if (lane == 31) ws[wid] = sc;
    __syncthreads();
    if (t < 8) {
        int v = ws[t];
#pragma unroll
        for (int o = 1; o < 8; o <<= 1) {
            int u = __shfl_up_sync(0xffu, v, o);
            if (t >= o) v += u;
        }
        ws[t] = v;
    }
    __syncthreads();
    int excl = sc - s + (wid ? ws[wid - 1] : 0);
    int4 rp;
    rp.x = excl; rp.y = excl + d.x; rp.z = rp.y + d.y; rp.w = rp.z + d.z;
    if (base + 3 < NN) *(int4*)&g_rowptr[base] = rp;
    else {
        if (base + 0 < NN) g_rowptr[base + 0] = rp.x;
        if (base + 1 < NN) g_rowptr[base + 1] = rp.y;
        if (base + 2 < NN) g_rowptr[base + 2] = rp.z;
    }
    if (t == 255) g_bsum[b] = excl + s;
}

__global__ void k_scan_tots(int nblk) {
    int lane = threadIdx.x;
    int carry = 0;
    for (int i = 0; i < 4; ++i) {
        int idx = i * 32 + lane;
        int v = idx < nblk ? g_bsum[idx] : 0;
        int sc = v;
#pragma unroll
        for (int o = 1; o < 32; o <<= 1) {
            int u = __shfl_up_sync(0xffffffffu, sc, o);
            if (lane >= o) sc += u;
        }
        if (idx < nblk) g_boff[idx] = carry + sc - v;
        carry += __shfl_sync(0xffffffffu, sc, 31);
    }
    if (lane == 0) g_rowptr[NN] = carry;
}

__global__ void k_scan_add() {
    int t = threadIdx.x, b = blockIdx.x;
    if (b == 0) return;
    int off = g_boff[b];
    int base = b * 1024 + t * 4;
    if (base + 3 < NN) {
        int4 rp = *(const int4*)&g_rowptr[base];
        rp.x += off; rp.y += off; rp.z += off; rp.w += off;
        *(int4*)&g_rowptr[base] = rp;
    } else {
        for (int i = 0; i < 4; ++i)
            if (base + i < NN) g_rowptr[base + i] += off;
    }
}

__global__ void k_fill(const int* __restrict__ ei) {
    int e = blockIdx.x * 256 + threadIdx.x;
    if (e >= EE) return;
    int r = ei[e];
    int c = ei[EE + e];
    int p = g_rowptr[c] + atomicAdd(&g_fill[c], 1);
    float v = g_dinv[r] * g_dinv[c];
    g_edge[p] = make_int2(r, __float_as_int(v));
}

// ===================== split-fp16 mma.sync GEMM =============================
// Z = A @ W^T + b, BN stats epilogue. W split x=xh+xl (fp16 pair) at smem
// load. A either fp32 (split, 3 MMA/step) or fp16 (exact, 2 MMA/step).

__device__ __forceinline__ void split_h2(float x, float y, uint32_t& hi, uint32_t& lo) {
    __half2 h = __floats2half2_rn(x, y);
    float2 hf = __half22float2(h);
    __half2 l = __floats2half2_rn(x - hf.x, y - hf.y);
    hi = *(uint32_t*)&h;
    lo = *(uint32_t*)&l;
}

__device__ __forceinline__ void mma16(float* d, const uint32_t* a, uint32_t b0, uint32_t b1) {
    asm volatile(
        "mma.sync.aligned.m16n8k16.row.col.f32.f16.f16.f32 "
        "{%0,%1,%2,%3}, {%4,%5,%6,%7}, {%8,%9}, {%0,%1,%2,%3};"
        : "+f"(d[0]), "+f"(d[1]), "+f"(d[2]), "+f"(d[3])
        : "r"(a[0]), "r"(a[1]), "r"(a[2]), "r"(a[3]), "r"(b0), "r"(b1));
}

#define GEMM_SMEM_F (4 * 128 * HST * 4 + 3 * 128 * 4)
#define GEMM_SMEM_H (3 * 128 * HST * 4 + 3 * 128 * 4)

template <bool AHALF>
__global__ __launch_bounds__(256)
void k_gemm_t(const void* __restrict__ Ain, const float* __restrict__ W,
              const float* __restrict__ bias, float* __restrict__ Z, int nrows) {
    extern __shared__ uint32_t smu[];
    uint32_t* sAh = smu;                                   // [128][HST]
    uint32_t* sAl = AHALF ? smu : smu + 128 * HST;         // unused if AHALF
    uint32_t* sBh = smu + (AHALF ? 1 : 2) * 128 * HST;
    uint32_t* sBl = sBh + 128 * HST;
    float* sSum  = (float*)(sBl + 128 * HST);
    float* sSq   = sSum + 128;
    float* sBias = sSq + 128;

    const int tid = threadIdx.x;
    const int wid = tid >> 5, lane = tid & 31;
    const int rowBase = blockIdx.x * 128;
    const int r = lane >> 2, c = lane & 3;

    if (AHALF) {
        const uint2* A2 = (const uint2*)Ain;
#pragma unroll
        for (int it = 0; it < 16; ++it) {
            int vec = tid + it * 256;
            int row = vec >> 5, q = vec & 31;    // q: uint2 (4 halves) index
            int gr = rowBase + row;
            uint2 u = make_uint2(0u, 0u);
            if (gr < nrows) u = A2[(size_t)gr * 32 + q];
            *(uint2*)&sAh[row * HST + 2 * q] = u;
        }
    } else {
        const float4* A4 = (const float4*)Ain;
#pragma unroll
        for (int it = 0; it < 16; ++it) {
            int vec = tid + it * 256;
            int row = vec >> 5, q = vec & 31;    // q: float4 index
            int gr = rowBase + row;
            float4 v = make_float4(0.f, 0.f, 0.f, 0.f);
            if (gr < nrows) v = ((const float4*)A4)[(size_t)gr * 32 + q];
            uint32_t h0, l0, h1, l1;
            split_h2(v.x, v.y, h0, l0);
            split_h2(v.z, v.w, h1, l1);
            int idx = row * HST + 2 * q;
            *(uint2*)&sAh[idx] = make_uint2(h0, h1);
            *(uint2*)&sAl[idx] = make_uint2(l0, l1);
        }
    }
    const float4* W4 = (const float4*)W;
#pragma unroll
    for (int it = 0; it < 16; ++it) {
        int vec = tid + it * 256;
        int row = vec >> 5, q = vec & 31;
        float4 v = W4[vec];
        uint32_t h0, l0, h1, l1;
        split_h2(v.x, v.y, h0, l0);
        split_h2(v.z, v.w, h1, l1);
        int idx = row * HST + 2 * q;
        *(uint2*)&sBh[idx] = make_uint2(h0, h1);
        *(uint2*)&sBl[idx] = make_uint2(l0, l1);
    }
    if (tid < 128) { sSum[tid] = 0.f; sSq[tid] = 0.f; sBias[tid] = bias[tid]; }
    __syncthreads();

    const int wm = wid & 3, wn = wid >> 2;
    float acc[2][8][4];
#pragma unroll
    for (int mt = 0; mt < 2; ++mt)
#pragma unroll
        for (int nt = 0; nt < 8; ++nt)
#pragma unroll
            for (int i = 0; i < 4; ++i) acc[mt][nt][i] = 0.f;

#pragma unroll 1
    for (int ks = 0; ks < 8; ++ks) {        // K=16 per step
        const int kb = ks * 8 + c;
        uint32_t ah[2][4], al[2][4];
#pragma unroll
        for (int mt = 0; mt < 2; ++mt) {
            int ba = (wm * 32 + mt * 16 + r) * HST + kb;
            ah[mt][0] = sAh[ba];
            ah[mt][1] = sAh[ba + 8 * HST];
            ah[mt][2] = sAh[ba + 4];
            ah[mt][3] = sAh[ba + 8 * HST + 4];
            if (!AHALF) {
                al[mt][0] = sAl[ba];
                al[mt][1] = sAl[ba + 8 * HST];
                al[mt][2] = sAl[ba + 4];
                al[mt][3] = sAl[ba + 8 * HST + 4];
            }
        }
#pragma unroll
        for (int nt = 0; nt < 8; ++nt) {
            int bb = (wn * 64 + nt * 8 + r) * HST + kb;
            uint32_t bh0 = sBh[bb], bh1 = sBh[bb + 4];
            uint32_t bl0 = sBl[bb], bl1 = sBl[bb + 4];
#pragma unroll
            for (int mt = 0; mt < 2; ++mt) {
                mma16(acc[mt][nt], ah[mt], bh0, bh1);
                mma16(acc[mt][nt], ah[mt], bl0, bl1);
                if (!AHALF) mma16(acc[mt][nt], al[mt], bh0, bh1);
            }
        }
    }

    // epilogue: bias add, store, BN stats
    float cs[16], cq[16];
#pragma unroll
    for (int i = 0; i < 16; ++i) { cs[i] = 0.f; cq[i] = 0.f; }

#pragma unroll
    for (int nt = 0; nt < 8; ++nt) {
        int C0 = wn * 64 + nt * 8 + 2 * c;
        float b0 = sBias[C0], b1 = sBias[C0 + 1];
#pragma unroll
        for (int mt = 0; mt < 2; ++mt) {
            int R0 = rowBase + wm * 32 + mt * 16 + r;
            int R1 = R0 + 8;
            if (R0 < nrows) {
                float z0 = acc[mt][nt][0] + b0;
                float z1 = acc[mt][nt][1] + b1;
                *(float2*)&Z[(size_t)R0 * 128 + C0] = make_float2(z0, z1);
                cs[2 * nt] += z0; cq[2 * nt] += z0 * z0;
                cs[2 * nt + 1] += z1; cq[2 * nt + 1] += z1 * z1;
            }
            if (R1 < nrows) {
                float z2 = acc[mt][nt][2] + b0;
                float z3 = acc[mt][nt][3] + b1;
                *(float2*)&Z[(size_t)R1 * 128 + C0] = make_float2(z2, z3);
                cs[2 * nt] += z2; cq[2 * nt] += z2 * z2;
                cs[2 * nt + 1] += z3; cq[2 * nt + 1] += z3 * z3;
            }
        }
    }
#pragma unroll
    for (int o = 4; o <= 16; o <<= 1) {
#pragma unroll
        for (int i = 0; i < 16; ++i) {
            cs[i] += __shfl_xor_sync(0xffffffffu, cs[i], o);
            cq[i] += __shfl_xor_sync(0xffffffffu, cq[i], o);
        }
    }
    if (r == 0) {
#pragma unroll
        for (int nt = 0; nt < 8; ++nt) {
            int C0 = wn * 64 + nt * 8 + 2 * c;
            atomicAdd(&sSum[C0],     cs[2 * nt]);
            atomicAdd(&sSum[C0 + 1], cs[2 * nt + 1]);
            atomicAdd(&sSq[C0],      cq[2 * nt]);
            atomicAdd(&sSq[C0 + 1],  cq[2 * nt + 1]);
        }
    }
    __syncthreads();
    if (tid < 128) {
        atomicAdd(&g_stats[tid], sSum[tid]);
        atomicAdd(&g_stats[128 + tid], sSq[tid]);
    }
}

// ========== BN prep (reads stats, then re-zeroes for next GEMM) ============
__global__ void k_bnprep(const float* __restrict__ gamma, const float* __restrict__ beta) {
    int j = threadIdx.x;
    if (j < DH) {
        float s = g_stats[j];
        float q = g_stats[128 + j];
        float mu = s * (1.0f / (float)NN);
        float var = q * (1.0f / (float)NN) - mu * mu;
        float rs = rsqrtf(var + BN_EPS);
        float sc = gamma[j] * rs;
        g_scale[j] = sc;
        g_shift[j] = beta[j] - mu * sc;
        g_stats[j] = 0.f;
        g_stats[128 + j] = 0.f;
    }
}

// ========== fused BN/ReLU/residual; fp16 residual input =====================
__global__ void k_bnfused(const float4* __restrict__ Z, const uint2* __restrict__ X0,
                          float4* __restrict__ OutF, uint2* __restrict__ OutH, int nvec) {
    int i = blockIdx.x * 256 + threadIdx.x;
    if (i >= nvec) return;
    int c4 = i & 31;
    float4 sc = ((const float4*)g_scale)[c4];
    float4 sh = ((const float4*)g_shift)[c4];
    float4 z = Z[i];
    float4 h;
    h.x = fmaxf(fmaf(z.x, sc.x, sh.x), 0.f);
    h.y = fmaxf(fmaf(z.y, sc.y, sh.y), 0.f);
    h.z = fmaxf(fmaf(z.z, sc.z, sh.z), 0.f);
    h.w = fmaxf(fmaf(z.w, sc.w, sh.w), 0.f);
    if (X0) {
        uint2 u = X0[i];
        float2 x0 = __half22float2(*(__half2*)&u.x);
        float2 x1 = __half22float2(*(__half2*)&u.y);
        h.x += x0.x; h.y += x0.y; h.z += x1.x; h.w += x1.y;
    }
    if (OutF) OutF[i] = h;
    if (OutH) {
        __half2 p0 = __floats2half2_rn(h.x, h.y);
        __half2 p1 = __floats2half2_rn(h.z, h.w);
        uint2 u;
        u.x = *(uint32_t*)&p0;
        u.y = *(uint32_t*)&p1;
        OutH[i] = u;
    }
}

// ===== SPMM: warp/node, fp16 gather, fp32 accumulate, fp16 store, MLP=4 ====
__device__ __forceinline__ void spmm_fma(float4& acc, float vj, uint2 u) {
    float2 f0 = __half22float2(*(__half2*)&u.x);
    float2 f1 = __half22float2(*(__half2*)&u.y);
    acc.x = fmaf(vj, f0.x, acc.x);
    acc.y = fmaf(vj, f0.y, acc.y);
    acc.z = fmaf(vj, f1.x, acc.z);
    acc.w = fmaf(vj, f1.y, acc.w);
}

__global__ void k_spmm(const uint2* __restrict__ H, uint2* __restrict__ O) {
    int gt = blockIdx.x * 256 + threadIdx.x;
    int w = gt >> 5;
    int lane = gt & 31;
    if (w >= NN) return;
    int rp0 = g_rowptr[w], rp1 = g_rowptr[w + 1];
    float4 acc = make_float4(0.f, 0.f, 0.f, 0.f);
    for (int base = rp0; base < rp1; base += 32) {
        int nb = min(32, rp1 - base);
        int s = 0; float v = 0.f;
        if (lane < nb) {
            int2 e = g_edge[base + lane];
            s = e.x; v = __int_as_float(e.y);
        }
        int j = 0;
#pragma unroll 1
        for (; j + 4 <= nb; j += 4) {
            int s0 = __shfl_sync(0xffffffffu, s, j);
            int s1 = __shfl_sync(0xffffffffu, s, j + 1);
            int s2 = __shfl_sync(0xffffffffu, s, j + 2);
            int s3 = __shfl_sync(0xffffffffu, s, j + 3);
            float v0 = __shfl_sync(0xffffffffu, v, j);
            float v1 = __shfl_sync(0xffffffffu, v, j + 1);
            float v2 = __shfl_sync(0xffffffffu, v, j + 2);
            float v3 = __shfl_sync(0xffffffffu, v, j + 3);
            uint2 u0 = H[(size_t)s0 * 32 + lane];
            uint2 u1 = H[(size_t)s1 * 32 + lane];
            uint2 u2 = H[(size_t)s2 * 32 + lane];
            uint2 u3 = H[(size_t)s3 * 32 + lane];
            spmm_fma(acc, v0, u0);
            spmm_fma(acc, v1, u1);
            spmm_fma(acc, v2, u2);
            spmm_fma(acc, v3, u3);
        }
        for (; j < nb; ++j) {
            int sj = __shfl_sync(0xffffffffu, s, j);
            float vj = __shfl_sync(0xffffffffu, v, j);
            spmm_fma(acc, vj, H[(size_t)sj * 32 + lane]);
        }
    }
    __half2 p0 = __floats2half2_rn(acc.x, acc.y);
    __half2 p1 = __floats2half2_rn(acc.z, acc.w);
    uint2 u;
    u.x = *(uint32_t*)&p0;
    u.y = *(uint32_t*)&p1;
    O[(size_t)w * 32 + lane] = u;
}

// ===================== classifier (N x 40, fp32) ============================
__global__ void k_cls(const float* __restrict__ A, const float* __restrict__ W,
                      const float* __restrict__ bias, float* __restrict__ O, int nrows) {
    extern __shared__ float sm[];
    float* As = sm;             // [128][128]
    float* Wt = sm + 16384;     // [128][40]
    const int tx = threadIdx.x, ty = threadIdx.y;
    const int tid = ty * 8 + tx;
    const int rowBase = blockIdx.x * 128;

    for (int idx = tid; idx < DOUT * DH; idx += 128) {
        int j = idx >> 7, k = idx & 127;
        Wt[k * DOUT + j] = W[idx];
    }
    const float4* A4 = (const float4*)A;
#pragma unroll
    for (int it = 0; it < 32; ++it) {
        int vec = tid + it * 128;
        int rr = vec >> 5, k4 = vec & 31;
        int grow = rowBase + rr;
        float4 a = make_float4(0.f, 0.f, 0.f, 0.f);
        if (grow < nrows) a = A4[(size_t)grow * 32 + k4];
        *(float4*)(As + rr * 128 + k4 * 4) = a;
    }
    __syncthreads();

    const int r0 = ty * 8, c0 = tx * 5;
    float acc[8][5];
#pragma unroll
    for (int r = 0; r < 8; ++r)
#pragma unroll
        for (int c = 0; c < 5; ++c) acc[r][c] = 0.f;

#pragma unroll 4
    for (int k = 0; k < 128; ++k) {
        float b[5];
#pragma unroll
        for (int c = 0; c < 5; ++c) b[c] = Wt[k * DOUT + c0 + c];
#pragma unroll
        for (int r = 0; r < 8; ++r) {
            float a = As[(r0 + r) * 128 + k];
#pragma unroll
            for (int c = 0; c < 5; ++c) acc[r][c] = fmaf(a, b[c], acc[r][c]);
        }
    }
    float bb[5];
#pragma unroll
    for (int c = 0; c < 5; ++c) bb[c] = bias[c0 + c];
#pragma unroll
    for (int r = 0; r < 8; ++r) {
        int grow = rowBase + r0 + r;
        if (grow < nrows) {
#pragma unroll
            for (int c = 0; c < 5; ++c)
                O[(size_t)grow * DOUT + c0 + c] = acc[r][c] + bb[c];
        }
    }
}

// ===================== driver ===============================================
extern "C" void kernel_launch(void* const* d_in, const int* in_sizes, int n_in,
                              void* d_out, int out_size) {
    const float* x      = (const float*)d_in[0];
    const int*   ei     = (const int*)d_in[1];
    const float* fc_w   = (const float*)d_in[2];
    const float* fc_b   = (const float*)d_in[3];
    const float* conv_w = (const float*)d_in[4];
    const float* conv_b = (const float*)d_in[5];
    const float* gamma  = (const float*)d_in[6];
    const float* beta   = (const float*)d_in[7];
    const float* cls_w  = (const float*)d_in[8];
    const float* cls_b  = (const float*)d_in[9];
    float* out = (float*)d_out;

    float *bA, *bB;
    __half *hH, *x0h, *aggH;
    cudaGetSymbolAddress((void**)&bA, g_bA);
    cudaGetSymbolAddress((void**)&bB, g_bB);
    cudaGetSymbolAddress((void**)&hH, g_hH);
    cudaGetSymbolAddress((void**)&x0h, g_x0h);
    cudaGetSymbolAddress((void**)&aggH, g_aggH);

    const int CLS_SMEM = 128 * 128 * 4 + DH * DOUT * 4;
    cudaFuncSetAttribute(k_gemm_t<false>, cudaFuncAttributeMaxDynamicSharedMemorySize, GEMM_SMEM_F);
    cudaFuncSetAttribute(k_gemm_t<true>,  cudaFuncAttributeMaxDynamicSharedMemorySize, GEMM_SMEM_H);
    cudaFuncSetAttribute(k_cls, cudaFuncAttributeMaxDynamicSharedMemorySize, CLS_SMEM);

    const int nodeBlocks = (NN + 255) / 256;
    const int edgeBlocks = (EE + 255) / 256;
    const int scanBlocks = (NN + 1023) / 1024;  // 98
    const int gemmGrid   = (NN + 127) / 128;    // 782
    const int vecBlocks  = (NN * 32) / 256;     // 12500

    // graph build
    k_zero_build<<<nodeBlocks, 256>>>();
    k_degree<<<edgeBlocks, 256>>>(ei);
    k_scan_part<<<scanBlocks, 256>>>();
    k_scan_tots<<<1, 32>>>(scanBlocks);
    k_scan_add<<<scanBlocks, 256>>>();
    k_fill<<<edgeBlocks, 256>>>(ei);

    // layer 0: fc -> bn0 -> relu ; x0 (fp16) doubles as h0 for SPMM1
    k_gemm_t<false><<<gemmGrid, 256, GEMM_SMEM_F>>>(x, fc_w, fc_b, bB, NN);
    k_bnprep<<<1, 128>>>(gamma, beta);
    k_bnfused<<<vecBlocks, 256>>>((const float4*)bB, (const uint2*)0,
                                  (float4*)0, (uint2*)x0h, NN * 32);

    for (int i = 0; i < 3; ++i) {
        const __half* hin = (i == 0) ? x0h : hH;
        k_spmm<<<vecBlocks, 256>>>((const uint2*)hin, (uint2*)aggH);
        k_gemm_t<true><<<gemmGrid, 256, GEMM_SMEM_H>>>(aggH, conv_w + i * DH * DH,
                                                       conv_b + i * DH, bB, NN);
        k_bnprep<<<1, 128>>>(gamma + (i + 1) * DH, beta + (i + 1) * DH);
        if (i < 2) {
            k_bnfused<<<vecBlocks, 256>>>((const float4*)bB, (const uint2*)x0h,
                                          (float4*)0, (uint2*)hH, NN * 32);
        } else {
            k_bnfused<<<vecBlocks, 256>>>((const float4*)bB, (const uint2*)x0h,
                                          (float4*)bA, (uint2*)0, NN * 32);
        }
    }

    k_cls<<<gemmGrid, dim3(8, 16), CLS_SMEM>>>(bA, cls_w, cls_b, out, NN);
}